// round 1
// baseline (speedup 1.0000x reference)
#include <cuda_runtime.h>
#include <cuda_bf16.h>
#include <cstdint>

// ---------------------------------------------------------------------------
// Sparse conv encoder:
//   f1 = leaky( sconv(x,  nmap1, W1, b1) )        N  rows, 96 -> 64, 27 taps
//   f2 = leaky( sconv(f1, nmap2, W2, b2) )        N2 rows, 64 -> 64,  8 taps
//   f2 = BN(f2) * scale                           batch stats over N2 rows
//   out = sconv(f2, nmap3, W3, b3)                N2 rows, 64 -> 64, 27 taps
// ---------------------------------------------------------------------------

#define MAXN 60032
__device__ float g_f1[MAXN * 64];
__device__ float g_f2[MAXN * 64];
__device__ float g_partial[128 * 128];   // [G][128]: sums + sumsqs per channel
__device__ float g_st[128];              // [0:64) scale a, [64:128) shift t

// ---------------------------------------------------------------------------
// Gather-GEMM: out[row, :64] = sum_k sum_c fin[nmap[row,k], c] * W[k, c, :64] + b
// Block: 64 rows x 64 cols, 256 threads, 4x4 micro-tile per thread.
// Sentinel nmap entries (idx >= n_in) gather zeros (no pad row needed).
// ---------------------------------------------------------------------------
template <int CIN, int KT, bool LEAKY>
__global__ __launch_bounds__(256) void sconv_kernel(
    const float* __restrict__ fin, int n_in,
    const int* __restrict__ nmap, int n_out,
    const float* __restrict__ W, const float* __restrict__ bias,
    float* __restrict__ fout)
{
    constexpr int BM = 64;
    constexpr int BN = 64;
    constexpr int LDA = CIN + 1;           // pad to avoid bank conflicts on A reads

    extern __shared__ float smem[];
    float* As = smem;                       // [BM][LDA]
    float* Bs = smem + BM * LDA;            // [CIN][BN]

    const int tid = threadIdx.x;
    const int tx  = tid & 15;               // 16 col-groups of 4
    const int ty  = tid >> 4;               // 16 row-groups of 4
    const int row0 = blockIdx.x * BM;

    float acc[4][4] = {};

    for (int k = 0; k < KT; ++k) {
        __syncthreads();   // previous iteration's compute must be done

        // ---- gather A: 64 rows x CIN, one warp handles 8 rows (strided) ----
        {
            const int lane = tid & 31;
            for (int r = tid >> 5; r < BM; r += 8) {
                const int rr = row0 + r;
                int idx = n_in;
                if (rr < n_out) idx = __ldg(&nmap[(size_t)rr * KT + k]);
                if (idx < n_in) {
                    const float* src = fin + (size_t)idx * CIN;
                    #pragma unroll
                    for (int c = lane; c < CIN; c += 32)
                        As[r * LDA + c] = __ldg(&src[c]);
                } else {
                    #pragma unroll
                    for (int c = lane; c < CIN; c += 32)
                        As[r * LDA + c] = 0.0f;
                }
            }
        }
        // ---- stage W tap: CIN x 64 ----
        {
            const float* wk = W + (size_t)k * CIN * BN;
            #pragma unroll
            for (int i = tid; i < CIN * BN; i += 256)
                Bs[i] = __ldg(&wk[i]);
        }
        __syncthreads();

        // ---- 64x64 += 64xCIN @ CINx64 ----
        #pragma unroll 8
        for (int c = 0; c < CIN; ++c) {
            const float4 bv = *reinterpret_cast<const float4*>(&Bs[c * BN + tx * 4]);
            float a[4];
            #pragma unroll
            for (int i = 0; i < 4; ++i) a[i] = As[(ty * 4 + i) * LDA + c];
            #pragma unroll
            for (int i = 0; i < 4; ++i) {
                acc[i][0] = fmaf(a[i], bv.x, acc[i][0]);
                acc[i][1] = fmaf(a[i], bv.y, acc[i][1]);
                acc[i][2] = fmaf(a[i], bv.z, acc[i][2]);
                acc[i][3] = fmaf(a[i], bv.w, acc[i][3]);
            }
        }
    }

    // ---- epilogue: bias (+ leaky), vectorized store ----
    const float4 bb = *reinterpret_cast<const float4*>(&bias[tx * 4]);
    #pragma unroll
    for (int i = 0; i < 4; ++i) {
        const int row = row0 + ty * 4 + i;
        if (row < n_out) {
            float4 v;
            v.x = acc[i][0] + bb.x;
            v.y = acc[i][1] + bb.y;
            v.z = acc[i][2] + bb.z;
            v.w = acc[i][3] + bb.w;
            if (LEAKY) {
                v.x = v.x >= 0.f ? v.x : 0.1f * v.x;
                v.y = v.y >= 0.f ? v.y : 0.1f * v.y;
                v.z = v.z >= 0.f ? v.z : 0.1f * v.z;
                v.w = v.w >= 0.f ? v.w : 0.1f * v.w;
            }
            *reinterpret_cast<float4*>(&fout[(size_t)row * BN + tx * 4]) = v;
        }
    }
}

// ---------------------------------------------------------------------------
// BatchNorm: deterministic two-pass reduction over N2 rows x 64 channels
// ---------------------------------------------------------------------------
__global__ __launch_bounds__(256) void bn_partial_kernel(
    const float* __restrict__ f, int n2, float* __restrict__ partial)
{
    const int tid = threadIdx.x;
    const int c = tid & 63;
    const int sub = tid >> 6;              // 0..3
    float s = 0.f, s2 = 0.f;
    for (int r = blockIdx.x * 4 + sub; r < n2; r += gridDim.x * 4) {
        const float v = f[(size_t)r * 64 + c];
        s += v;
        s2 += v * v;
    }
    __shared__ float sh[256], sh2[256];
    sh[tid] = s; sh2[tid] = s2;
    __syncthreads();
    if (tid < 64) {
        s  = sh[tid]  + sh[tid + 64]  + sh[tid + 128]  + sh[tid + 192];
        s2 = sh2[tid] + sh2[tid + 64] + sh2[tid + 128] + sh2[tid + 192];
        partial[blockIdx.x * 128 + tid]      = s;
        partial[blockIdx.x * 128 + 64 + tid] = s2;
    }
}

__global__ void bn_finalize_kernel(
    const float* __restrict__ partial, int G, int n2,
    const float* __restrict__ gamma, const float* __restrict__ beta,
    const float* __restrict__ scale, float* __restrict__ st)
{
    const int c = threadIdx.x;             // 64 threads
    float s = 0.f, s2 = 0.f;
    for (int g = 0; g < G; ++g) {
        s  += partial[g * 128 + c];
        s2 += partial[g * 128 + 64 + c];
    }
    const float inv_n = 1.0f / (float)n2;
    const float mu  = s * inv_n;
    const float var = fmaxf(s2 * inv_n - mu * mu, 0.f);
    const float r   = rsqrtf(var + 1e-5f);
    const float sc  = scale[0];
    const float a   = gamma[c] * r * sc;
    st[c]      = a;
    st[64 + c] = (beta[c] - mu * gamma[c] * r) * sc;
}

__global__ __launch_bounds__(256) void bn_apply_kernel(
    float* __restrict__ f, int n2, const float* __restrict__ st)
{
    const int i = blockIdx.x * 256 + threadIdx.x;
    if (i < n2 * 64) {
        const int c = i & 63;
        f[i] = fmaf(f[i], st[c], st[64 + c]);
    }
}

// ---------------------------------------------------------------------------
extern "C" void kernel_launch(void* const* d_in, const int* in_sizes, int n_in_arrs,
                              void* d_out, int out_size)
{
    const float* x     = (const float*)d_in[0];
    const float* W1    = (const float*)d_in[1];
    const float* b1    = (const float*)d_in[2];
    const float* W2    = (const float*)d_in[3];
    const float* b2    = (const float*)d_in[4];
    const float* W3    = (const float*)d_in[5];
    const float* b3    = (const float*)d_in[6];
    const float* gamma = (const float*)d_in[7];
    const float* beta  = (const float*)d_in[8];
    const float* scale = (const float*)d_in[9];
    const int* nmap1   = (const int*)d_in[10];
    const int* nmap2   = (const int*)d_in[11];
    const int* nmap3   = (const int*)d_in[12];

    const int N  = in_sizes[0] / 96;       // stride-1 points
    const int N2 = in_sizes[11] / 8;       // stride-2 points

    float *f1, *f2, *partial, *st;
    cudaGetSymbolAddress((void**)&f1, g_f1);
    cudaGetSymbolAddress((void**)&f2, g_f2);
    cudaGetSymbolAddress((void**)&partial, g_partial);
    cudaGetSymbolAddress((void**)&st, g_st);

    // conv1: 96 -> 64, 27 taps, leaky
    {
        constexpr int smem = 64 * 97 * 4 + 96 * 64 * 4;   // 49408 B
        cudaFuncSetAttribute(sconv_kernel<96, 27, true>,
                             cudaFuncAttributeMaxDynamicSharedMemorySize, smem);
        sconv_kernel<96, 27, true><<<(N + 63) / 64, 256, smem>>>(
            x, N, nmap1, N, W1, b1, f1);
    }
    // conv2: 64 -> 64, 8 taps, leaky
    {
        constexpr int smem = 64 * 65 * 4 + 64 * 64 * 4;   // 33024 B
        cudaFuncSetAttribute(sconv_kernel<64, 8, true>,
                             cudaFuncAttributeMaxDynamicSharedMemorySize, smem);
        sconv_kernel<64, 8, true><<<(N2 + 63) / 64, 256, smem>>>(
            f1, N, nmap2, N2, W2, b2, f2);
    }
    // batch norm (train-mode batch stats) + scale, in place on f2
    {
        const int G = 120;
        bn_partial_kernel<<<G, 256>>>(f2, N2, partial);
        bn_finalize_kernel<<<1, 64>>>(partial, G, N2, gamma, beta, scale, st);
        bn_apply_kernel<<<(N2 * 64 + 255) / 256, 256>>>(f2, N2, st);
    }
    // conv3: 64 -> 64, 27 taps, no activation, straight to d_out
    {
        constexpr int smem = 64 * 65 * 4 + 64 * 64 * 4;
        cudaFuncSetAttribute(sconv_kernel<64, 27, false>,
                             cudaFuncAttributeMaxDynamicSharedMemorySize, smem);
        sconv_kernel<64, 27, false><<<(N2 + 63) / 64, 256, smem>>>(
            f2, N2, nmap3, N2, W3, b3, (float*)d_out);
    }
}

// round 4
// speedup vs baseline: 1.6354x; 1.6354x over previous
#include <cuda_runtime.h>
#include <cuda_bf16.h>
#include <cstdint>

// ===========================================================================
// Sparse conv encoder on tensor cores via mma.sync (bf16 hi/lo x3, fp32 acc)
//   f1 = leaky( sconv(x,  nmap1, W1, b1) )   N  rows, 96 -> 64, 27 taps
//   f2 = leaky( sconv(f1, nmap2, W2, b2) )   N2 rows, 64 -> 64,  8 taps
//   f2 = BN(f2) * scale
//   out = sconv(f2, nmap3, W3, b3)           N2 rows, 64 -> 64, 27 taps
// Features/weights stored as bf16 (hi, lo): v = hi + lo (err ~2^-17).
// GEMM accumulates Ahi*Bhi + Ahi*Blo + Alo*Bhi in fp32.
// ===========================================================================

#define MAXN 60032
__device__ __nv_bfloat16 g_x_hi[MAXN * 96];
__device__ __nv_bfloat16 g_x_lo[MAXN * 96];
__device__ __nv_bfloat16 g_f1_hi[MAXN * 64];
__device__ __nv_bfloat16 g_f1_lo[MAXN * 64];
__device__ __nv_bfloat16 g_f2_hi[MAXN * 64];
__device__ __nv_bfloat16 g_f2_lo[MAXN * 64];
__device__ __nv_bfloat16 g_w1_hi[27 * 96 * 64];
__device__ __nv_bfloat16 g_w1_lo[27 * 96 * 64];
__device__ __nv_bfloat16 g_w2_hi[8 * 64 * 64];
__device__ __nv_bfloat16 g_w2_lo[8 * 64 * 64];
__device__ __nv_bfloat16 g_w3_hi[27 * 64 * 64];
__device__ __nv_bfloat16 g_w3_lo[27 * 64 * 64];
__device__ float g_partial[128 * 128];
__device__ float g_st[128];

__device__ __forceinline__ uint32_t smem_u32(const void* p) {
    uint32_t a;
    asm("{ .reg .u64 t; cvta.to.shared.u64 t, %1; cvt.u32.u64 %0, t; }"
        : "=r"(a) : "l"(p));
    return a;
}

__device__ __forceinline__ void ldsm_x4(uint32_t* r, uint32_t addr) {
    asm volatile("ldmatrix.sync.aligned.m8n8.x4.shared.b16 {%0,%1,%2,%3}, [%4];"
                 : "=r"(r[0]), "=r"(r[1]), "=r"(r[2]), "=r"(r[3]) : "r"(addr));
}
__device__ __forceinline__ void ldsm_x4_t(uint32_t* r, uint32_t addr) {
    asm volatile("ldmatrix.sync.aligned.m8n8.x4.trans.shared.b16 {%0,%1,%2,%3}, [%4];"
                 : "=r"(r[0]), "=r"(r[1]), "=r"(r[2]), "=r"(r[3]) : "r"(addr));
}
__device__ __forceinline__ void mma_bf16(float* d, const uint32_t* a, const uint32_t* b) {
    asm volatile(
        "mma.sync.aligned.m16n8k16.row.col.f32.bf16.bf16.f32 "
        "{%0,%1,%2,%3}, {%4,%5,%6,%7}, {%8,%9}, {%0,%1,%2,%3};"
        : "+f"(d[0]), "+f"(d[1]), "+f"(d[2]), "+f"(d[3])
        : "r"(a[0]), "r"(a[1]), "r"(a[2]), "r"(a[3]), "r"(b[0]), "r"(b[1]));
}

// ---------------------------------------------------------------------------
// Gather-GEMM: 128 rows x 64 cols per CTA, 8 warps (4x2), m16n8k16 micro-tiles
// ---------------------------------------------------------------------------
template <int CIN, int KT, bool LEAKY, bool SPLIT_OUT>
__global__ __launch_bounds__(256, 2) void sconv_mma(
    const __nv_bfloat16* __restrict__ a_hi, const __nv_bfloat16* __restrict__ a_lo,
    int n_in, const int* __restrict__ nmap, int n_out,
    const __nv_bfloat16* __restrict__ w_hi, const __nv_bfloat16* __restrict__ w_lo,
    const float* __restrict__ bias,
    __nv_bfloat16* __restrict__ o_hi, __nv_bfloat16* __restrict__ o_lo,
    float* __restrict__ o_f32)
{
    constexpr int LDA = CIN + 8;             // halves; pad -> conflict-free ldmatrix
    constexpr int LDB = 72;                  // halves (64 + 8 pad)
    constexpr int KSTEPS = CIN / 16;
    constexpr int A_HALVES = 128 * LDA;      // one A buffer (hi or lo)
    constexpr int B_HALVES = CIN * LDB;
    // byte offsets of the four SMEM regions
    constexpr uint32_t OFF_ALO = (uint32_t)A_HALVES * 2;
    constexpr uint32_t OFF_BHI = (uint32_t)(2 * A_HALVES) * 2;
    constexpr uint32_t OFF_BLO = (uint32_t)(2 * A_HALVES + B_HALVES) * 2;

    extern __shared__ __align__(16) __nv_bfloat16 smem[];
    __nv_bfloat16* const As_hi = smem;
    __nv_bfloat16* const As_lo = smem + A_HALVES;
    __nv_bfloat16* const Bs_hi = smem + 2 * A_HALVES;
    __nv_bfloat16* const Bs_lo = smem + 2 * A_HALVES + B_HALVES;

    const int tid  = threadIdx.x;
    const int wid  = tid >> 5;
    const int lane = tid & 31;
    const int row0 = blockIdx.x * 128;
    const int wm   = (wid >> 1) * 32;        // warp row base in tile
    const int wn   = (wid & 1) * 32;         // warp col base

    float acc[2][4][4] = {};                 // [m-tile][n-tile][reg]

    const uint32_t sb = smem_u32(smem);
    const int lrow = lane & 15, lcol8 = (lane >> 4) * 8;

    for (int t = 0; t < KT; ++t) {
        __syncthreads();                     // prior MMA phase done

        // ---- gather A: 16 rows per warp ----
        #pragma unroll 4
        for (int j = 0; j < 16; ++j) {
            const int r  = wid * 16 + j;
            const int rr = row0 + r;
            int idx = n_in;
            if (rr < n_out) idx = __ldg(&nmap[(size_t)rr * KT + t]);
            uint32_t* dh = (uint32_t*)(As_hi + r * LDA);
            uint32_t* dl = (uint32_t*)(As_lo + r * LDA);
            if (idx < n_in) {
                const uint32_t* sh = (const uint32_t*)(a_hi + (size_t)idx * CIN);
                const uint32_t* sl = (const uint32_t*)(a_lo + (size_t)idx * CIN);
                #pragma unroll
                for (int i = lane; i < CIN / 2; i += 32) {
                    dh[i] = __ldg(&sh[i]);
                    dl[i] = __ldg(&sl[i]);
                }
            } else {
                #pragma unroll
                for (int i = lane; i < CIN / 2; i += 32) { dh[i] = 0u; dl[i] = 0u; }
            }
        }
        // ---- stage B tap: [CIN][64] -> [CIN][LDB] ----
        {
            const uint32_t* sh = (const uint32_t*)(w_hi + (size_t)t * CIN * 64);
            const uint32_t* sl = (const uint32_t*)(w_lo + (size_t)t * CIN * 64);
            #pragma unroll
            for (int i = tid; i < CIN * 32; i += 256) {
                const int r = i >> 5, c = i & 31;
                ((uint32_t*)(Bs_hi + r * LDB))[c] = __ldg(&sh[i]);
                ((uint32_t*)(Bs_lo + r * LDB))[c] = __ldg(&sl[i]);
            }
        }
        __syncthreads();

        // ---- MMA phase ----
        #pragma unroll
        for (int s = 0; s < KSTEPS; ++s) {
            uint32_t ah[2][4], al[2][4];      // A frags, 2 m-tiles
            #pragma unroll
            for (int mt = 0; mt < 2; ++mt) {
                const uint32_t off = (uint32_t)((wm + mt * 16 + lrow) * LDA
                                                + s * 16 + lcol8) * 2;
                ldsm_x4(ah[mt], sb + off);
                ldsm_x4(al[mt], sb + OFF_ALO + off);
            }
            uint32_t bh[2][4], bl[2][4];      // B frags, 2 pairs of n8 tiles
            #pragma unroll
            for (int p = 0; p < 2; ++p) {
                const uint32_t off = (uint32_t)((s * 16 + lrow) * LDB
                                                + wn + p * 16 + lcol8) * 2;
                ldsm_x4_t(bh[p], sb + OFF_BHI + off);
                ldsm_x4_t(bl[p], sb + OFF_BLO + off);
            }
            #pragma unroll
            for (int mt = 0; mt < 2; ++mt)
                #pragma unroll
                for (int nt = 0; nt < 4; ++nt) {
                    const uint32_t* Bh = &bh[nt >> 1][(nt & 1) * 2];
                    const uint32_t* Bl = &bl[nt >> 1][(nt & 1) * 2];
                    mma_bf16(acc[mt][nt], ah[mt], Bh);
                    mma_bf16(acc[mt][nt], ah[mt], Bl);
                    mma_bf16(acc[mt][nt], al[mt], Bh);
                }
        }
    }

    // ---- epilogue ----
    #pragma unroll
    for (int mt = 0; mt < 2; ++mt)
        #pragma unroll
        for (int nt = 0; nt < 4; ++nt)
            #pragma unroll
            for (int h = 0; h < 2; ++h) {     // h=0: rows 0-7, h=1: rows 8-15
                const int row = row0 + wm + mt * 16 + h * 8 + (lane >> 2);
                if (row >= n_out) continue;
                const int col = wn + nt * 8 + (lane & 3) * 2;
                float v0 = acc[mt][nt][h * 2]     + __ldg(&bias[col]);
                float v1 = acc[mt][nt][h * 2 + 1] + __ldg(&bias[col + 1]);
                if (LEAKY) {
                    v0 = v0 >= 0.f ? v0 : 0.1f * v0;
                    v1 = v1 >= 0.f ? v1 : 0.1f * v1;
                }
                if (SPLIT_OUT) {
                    __nv_bfloat162 hh, ll;
                    hh.x = __float2bfloat16_rn(v0);
                    hh.y = __float2bfloat16_rn(v1);
                    ll.x = __float2bfloat16_rn(v0 - __bfloat162float(hh.x));
                    ll.y = __float2bfloat16_rn(v1 - __bfloat162float(hh.y));
                    *(uint32_t*)(o_hi + (size_t)row * 64 + col) = *(uint32_t*)&hh;
                    *(uint32_t*)(o_lo + (size_t)row * 64 + col) = *(uint32_t*)&ll;
                } else {
                    float2 v; v.x = v0; v.y = v1;
                    *(float2*)(o_f32 + (size_t)row * 64 + col) = v;
                }
            }
}

// ---------------------------------------------------------------------------
// Prep: split fp32 -> bf16 hi/lo (weights keep native [tap][cin][64] layout)
// ---------------------------------------------------------------------------
__global__ __launch_bounds__(256) void split_kernel(
    const float* __restrict__ src, __nv_bfloat16* __restrict__ hi,
    __nv_bfloat16* __restrict__ lo, int n)
{
    for (int i = blockIdx.x * 256 + threadIdx.x; i < n; i += gridDim.x * 256) {
        const float v = src[i];
        const __nv_bfloat16 h = __float2bfloat16_rn(v);
        hi[i] = h;
        lo[i] = __float2bfloat16_rn(v - __bfloat162float(h));
    }
}

// ---------------------------------------------------------------------------
// BatchNorm (deterministic two-pass) on bf16 hi/lo storage
// ---------------------------------------------------------------------------
__global__ __launch_bounds__(256) void bn_partial_kernel(
    const __nv_bfloat16* __restrict__ fh, const __nv_bfloat16* __restrict__ fl,
    int n2, float* __restrict__ partial)
{
    const int tid = threadIdx.x;
    const int c = tid & 63;
    const int sub = tid >> 6;
    float s = 0.f, s2 = 0.f;
    for (int r = blockIdx.x * 4 + sub; r < n2; r += gridDim.x * 4) {
        const size_t i = (size_t)r * 64 + c;
        const float v = __bfloat162float(fh[i]) + __bfloat162float(fl[i]);
        s += v; s2 += v * v;
    }
    __shared__ float sh[256], sh2[256];
    sh[tid] = s; sh2[tid] = s2;
    __syncthreads();
    if (tid < 64) {
        s  = sh[tid]  + sh[tid + 64]  + sh[tid + 128]  + sh[tid + 192];
        s2 = sh2[tid] + sh2[tid + 64] + sh2[tid + 128] + sh2[tid + 192];
        partial[blockIdx.x * 128 + tid]      = s;
        partial[blockIdx.x * 128 + 64 + tid] = s2;
    }
}

__global__ void bn_finalize_kernel(
    const float* __restrict__ partial, int G, int n2,
    const float* __restrict__ gamma, const float* __restrict__ beta,
    const float* __restrict__ scale, float* __restrict__ st)
{
    const int c = threadIdx.x;
    float s = 0.f, s2 = 0.f;
    for (int g = 0; g < G; ++g) {
        s  += partial[g * 128 + c];
        s2 += partial[g * 128 + 64 + c];
    }
    const float inv_n = 1.0f / (float)n2;
    const float mu  = s * inv_n;
    const float var = fmaxf(s2 * inv_n - mu * mu, 0.f);
    const float r   = rsqrtf(var + 1e-5f);
    const float sc  = scale[0];
    st[c]      = gamma[c] * r * sc;
    st[64 + c] = (beta[c] - mu * gamma[c] * r) * sc;
}

__global__ __launch_bounds__(256) void bn_apply_kernel(
    __nv_bfloat16* __restrict__ fh, __nv_bfloat16* __restrict__ fl,
    int n2, const float* __restrict__ st)
{
    const int i = blockIdx.x * 256 + threadIdx.x;
    if (i < n2 * 64) {
        const int c = i & 63;
        const float v = fmaf(__bfloat162float(fh[i]) + __bfloat162float(fl[i]),
                             st[c], st[64 + c]);
        const __nv_bfloat16 h = __float2bfloat16_rn(v);
        fh[i] = h;
        fl[i] = __float2bfloat16_rn(v - __bfloat162float(h));
    }
}

// ---------------------------------------------------------------------------
extern "C" void kernel_launch(void* const* d_in, const int* in_sizes, int n_in_arrs,
                              void* d_out, int out_size)
{
    const float* x     = (const float*)d_in[0];
    const float* W1    = (const float*)d_in[1];
    const float* b1    = (const float*)d_in[2];
    const float* W2    = (const float*)d_in[3];
    const float* b2    = (const float*)d_in[4];
    const float* W3    = (const float*)d_in[5];
    const float* b3    = (const float*)d_in[6];
    const float* gamma = (const float*)d_in[7];
    const float* beta  = (const float*)d_in[8];
    const float* scale = (const float*)d_in[9];
    const int* nmap1   = (const int*)d_in[10];
    const int* nmap2   = (const int*)d_in[11];
    const int* nmap3   = (const int*)d_in[12];

    const int N  = in_sizes[0] / 96;
    const int N2 = in_sizes[11] / 8;

    __nv_bfloat16 *xh, *xl, *f1h, *f1l, *f2h, *f2l, *w1h, *w1l, *w2h, *w2l, *w3h, *w3l;
    float *partial, *st;
    cudaGetSymbolAddress((void**)&xh, g_x_hi);   cudaGetSymbolAddress((void**)&xl, g_x_lo);
    cudaGetSymbolAddress((void**)&f1h, g_f1_hi); cudaGetSymbolAddress((void**)&f1l, g_f1_lo);
    cudaGetSymbolAddress((void**)&f2h, g_f2_hi); cudaGetSymbolAddress((void**)&f2l, g_f2_lo);
    cudaGetSymbolAddress((void**)&w1h, g_w1_hi); cudaGetSymbolAddress((void**)&w1l, g_w1_lo);
    cudaGetSymbolAddress((void**)&w2h, g_w2_hi); cudaGetSymbolAddress((void**)&w2l, g_w2_lo);
    cudaGetSymbolAddress((void**)&w3h, g_w3_hi); cudaGetSymbolAddress((void**)&w3l, g_w3_lo);
    cudaGetSymbolAddress((void**)&partial, g_partial);
    cudaGetSymbolAddress((void**)&st, g_st);

    // prep: split inputs and weights to bf16 hi/lo
    split_kernel<<<512, 256>>>(x, xh, xl, N * 96);
    split_kernel<<<256, 256>>>(W1, w1h, w1l, 27 * 96 * 64);
    split_kernel<<<64,  256>>>(W2, w2h, w2l, 8 * 64 * 64);
    split_kernel<<<128, 256>>>(W3, w3h, w3l, 27 * 64 * 64);

    // conv1: 96 -> 64, 27 taps, leaky, split-out
    {
        constexpr int smem = (2 * 128 * (96 + 8) + 2 * 96 * 72) * 2;  // 80,896 B
        cudaFuncSetAttribute(sconv_mma<96, 27, true, true>,
                             cudaFuncAttributeMaxDynamicSharedMemorySize, smem);
        sconv_mma<96, 27, true, true><<<(N + 127) / 128, 256, smem>>>(
            xh, xl, N, nmap1, N, w1h, w1l, b1, f1h, f1l, nullptr);
    }
    // conv2: 64 -> 64, 8 taps, leaky, split-out
    {
        constexpr int smem = (2 * 128 * 72 + 2 * 64 * 72) * 2;        // 55,296 B
        cudaFuncSetAttribute(sconv_mma<64, 8, true, true>,
                             cudaFuncAttributeMaxDynamicSharedMemorySize, smem);
        sconv_mma<64, 8, true, true><<<(N2 + 127) / 128, 256, smem>>>(
            f1h, f1l, N, nmap2, N2, w2h, w2l, b2, f2h, f2l, nullptr);
    }
    // batch norm + scale, in place on f2 hi/lo
    {
        const int G = 120;
        bn_partial_kernel<<<G, 256>>>(f2h, f2l, N2, partial);
        bn_finalize_kernel<<<1, 64>>>(partial, G, N2, gamma, beta, scale, st);
        bn_apply_kernel<<<(N2 * 64 + 255) / 256, 256>>>(f2h, f2l, N2, st);
    }
    // conv3: 64 -> 64, 27 taps, fp32 out
    {
        constexpr int smem = (2 * 128 * 72 + 2 * 64 * 72) * 2;
        cudaFuncSetAttribute(sconv_mma<64, 27, false, false>,
                             cudaFuncAttributeMaxDynamicSharedMemorySize, smem);
        sconv_mma<64, 27, false, false><<<(N2 + 127) / 128, 256, smem>>>(
            f2h, f2l, N2, nmap3, N2, w3h, w3l, b3, nullptr, nullptr, (float*)d_out);
    }
}

// round 5
// speedup vs baseline: 1.9787x; 1.2099x over previous
#include <cuda_runtime.h>
#include <cuda_bf16.h>
#include <cstdint>

// ===========================================================================
// Sparse conv encoder, mma.sync bf16 hi/lo x3, cp.async double-buffered taps
//   f1 = leaky( sconv(x,  nmap1, W1, b1) )   N  rows, 96 -> 64, 27 taps
//   f2 = leaky( sconv(f1, nmap2, W2, b2) )   N2 rows, 64 -> 64,  8 taps
//   f2 = BN(f2) * scale
//   out = sconv(f2, nmap3, W3, b3)           N2 rows, 64 -> 64, 27 taps
// ===========================================================================

#define MAXN 60032
__device__ __nv_bfloat16 g_x_hi[MAXN * 96];
__device__ __nv_bfloat16 g_x_lo[MAXN * 96];
__device__ __nv_bfloat16 g_f1_hi[MAXN * 64];
__device__ __nv_bfloat16 g_f1_lo[MAXN * 64];
__device__ __nv_bfloat16 g_f2_hi[MAXN * 64];
__device__ __nv_bfloat16 g_f2_lo[MAXN * 64];
__device__ __nv_bfloat16 g_w1_hi[27 * 96 * 64];
__device__ __nv_bfloat16 g_w1_lo[27 * 96 * 64];
__device__ __nv_bfloat16 g_w2_hi[8 * 64 * 64];
__device__ __nv_bfloat16 g_w2_lo[8 * 64 * 64];
__device__ __nv_bfloat16 g_w3_hi[27 * 64 * 64];
__device__ __nv_bfloat16 g_w3_lo[27 * 64 * 64];
__device__ float g_partial[128 * 128];
__device__ float g_st[128];

__device__ __forceinline__ uint32_t smem_u32(const void* p) {
    uint32_t a;
    asm("{ .reg .u64 t; cvta.to.shared.u64 t, %1; cvt.u32.u64 %0, t; }"
        : "=r"(a) : "l"(p));
    return a;
}
__device__ __forceinline__ void cp16(uint32_t s, const void* g, int sz) {
    asm volatile("cp.async.cg.shared.global [%0], [%1], 16, %2;"
                 :: "r"(s), "l"(g), "r"(sz) : "memory");
}
__device__ __forceinline__ void cp_commit() {
    asm volatile("cp.async.commit_group;" ::: "memory");
}
template <int N>
__device__ __forceinline__ void cp_wait() {
    asm volatile("cp.async.wait_group %0;" :: "n"(N) : "memory");
}
__device__ __forceinline__ void ldsm_x4(uint32_t* r, uint32_t addr) {
    asm volatile("ldmatrix.sync.aligned.m8n8.x4.shared.b16 {%0,%1,%2,%3}, [%4];"
                 : "=r"(r[0]), "=r"(r[1]), "=r"(r[2]), "=r"(r[3]) : "r"(addr));
}
__device__ __forceinline__ void ldsm_x4_t(uint32_t* r, uint32_t addr) {
    asm volatile("ldmatrix.sync.aligned.m8n8.x4.trans.shared.b16 {%0,%1,%2,%3}, [%4];"
                 : "=r"(r[0]), "=r"(r[1]), "=r"(r[2]), "=r"(r[3]) : "r"(addr));
}
__device__ __forceinline__ void mma_bf16(float* d, const uint32_t* a, const uint32_t* b) {
    asm volatile(
        "mma.sync.aligned.m16n8k16.row.col.f32.bf16.bf16.f32 "
        "{%0,%1,%2,%3}, {%4,%5,%6,%7}, {%8,%9}, {%0,%1,%2,%3};"
        : "+f"(d[0]), "+f"(d[1]), "+f"(d[2]), "+f"(d[3])
        : "r"(a[0]), "r"(a[1]), "r"(a[2]), "r"(a[3]), "r"(b[0]), "r"(b[1]));
}

// ---------------------------------------------------------------------------
// Gather-GEMM: 128 rows x 64 cols per CTA, 8 warps (4x2), m16n8k16 tiles,
// 2-stage cp.async tap pipeline.
// ---------------------------------------------------------------------------
template <int CIN, int KT, bool LEAKY, bool SPLIT_OUT>
__global__ __launch_bounds__(256) void sconv_mma(
    const __nv_bfloat16* __restrict__ a_hi, const __nv_bfloat16* __restrict__ a_lo,
    int n_in, const int* __restrict__ nmap, int n_out,
    const __nv_bfloat16* __restrict__ w_hi, const __nv_bfloat16* __restrict__ w_lo,
    const float* __restrict__ bias,
    __nv_bfloat16* __restrict__ o_hi, __nv_bfloat16* __restrict__ o_lo,
    float* __restrict__ o_f32)
{
    constexpr int LDA = CIN + 8;                       // halves
    constexpr int LDB = 72;                            // halves
    constexpr int KSTEPS = CIN / 16;
    constexpr int CPR = CIN / 8;                       // 16B chunks per A row
    constexpr int A_HALVES = 128 * LDA;
    constexpr int B_HALVES = CIN * LDB;
    constexpr uint32_t OFF_ALO = (uint32_t)A_HALVES * 2;
    constexpr uint32_t OFF_BHI = (uint32_t)(2 * A_HALVES) * 2;
    constexpr uint32_t OFF_BLO = (uint32_t)(2 * A_HALVES + B_HALVES) * 2;
    constexpr uint32_t STAGE   = (uint32_t)(2 * A_HALVES + 2 * B_HALVES) * 2;

    extern __shared__ __align__(16) __nv_bfloat16 smem[];
    const uint32_t sb = smem_u32(smem);

    const int tid  = threadIdx.x;
    const int wid  = tid >> 5;
    const int lane = tid & 31;
    const int row0 = blockIdx.x * 128;
    const int wm   = (wid >> 1) * 32;
    const int wn   = (wid & 1) * 32;
    const int lrow = lane & 15, lcol8 = (lane >> 4) * 8;

    float acc[2][4][4] = {};

    // ---- prefetch one tap into stage st ----
    auto prefetch = [&](int t, uint32_t stoff) {
        // A: 2 bufs x 128 rows x CPR chunks
        #pragma unroll 2
        for (int i = tid; i < 2 * 128 * CPR; i += 256) {
            const int buf = i / (128 * CPR);
            const int j   = i % (128 * CPR);
            const int r   = j / CPR, c = j % CPR;
            const int rr  = row0 + r;
            int idx = n_in;
            if (rr < n_out) idx = __ldg(&nmap[(size_t)rr * KT + t]);
            const int ok = idx < n_in;
            const __nv_bfloat16* src = (buf ? a_lo : a_hi)
                + (size_t)(ok ? idx : 0) * CIN + c * 8;
            const uint32_t d = sb + stoff + (buf ? OFF_ALO : 0u)
                + (uint32_t)(r * LDA + c * 8) * 2;
            cp16(d, src, ok ? 16 : 0);
        }
        // B: 2 bufs x CIN rows x 8 chunks
        #pragma unroll 2
        for (int i = tid; i < 2 * CIN * 8; i += 256) {
            const int buf = i / (CIN * 8);
            const int j   = i % (CIN * 8);
            const int r   = j >> 3, c = j & 7;
            const __nv_bfloat16* src = (buf ? w_lo : w_hi)
                + (size_t)t * CIN * 64 + r * 64 + c * 8;
            const uint32_t d = sb + stoff + (buf ? OFF_BLO : OFF_BHI)
                + (uint32_t)(r * LDB + c * 8) * 2;
            cp16(d, src, 16);
        }
    };

    prefetch(0, 0);
    cp_commit();

    for (int t = 0; t < KT; ++t) {
        const uint32_t stoff = (t & 1) ? STAGE : 0u;
        if (t + 1 < KT) {
            prefetch(t + 1, (t & 1) ? 0u : STAGE);
            cp_commit();
            cp_wait<1>();
        } else {
            cp_wait<0>();
        }
        __syncthreads();

        // ---- MMA phase on stage t ----
        #pragma unroll
        for (int s = 0; s < KSTEPS; ++s) {
            uint32_t ah[2][4], al[2][4];
            #pragma unroll
            for (int mt = 0; mt < 2; ++mt) {
                const uint32_t off = (uint32_t)((wm + mt * 16 + lrow) * LDA
                                                + s * 16 + lcol8) * 2;
                ldsm_x4(ah[mt], sb + stoff + off);
                ldsm_x4(al[mt], sb + stoff + OFF_ALO + off);
            }
            uint32_t bh[2][4], bl[2][4];
            #pragma unroll
            for (int p = 0; p < 2; ++p) {
                const uint32_t off = (uint32_t)((s * 16 + lrow) * LDB
                                                + wn + p * 16 + lcol8) * 2;
                ldsm_x4_t(bh[p], sb + stoff + OFF_BHI + off);
                ldsm_x4_t(bl[p], sb + stoff + OFF_BLO + off);
            }
            #pragma unroll
            for (int mt = 0; mt < 2; ++mt)
                #pragma unroll
                for (int nt = 0; nt < 4; ++nt) {
                    const uint32_t* Bh = &bh[nt >> 1][(nt & 1) * 2];
                    const uint32_t* Bl = &bl[nt >> 1][(nt & 1) * 2];
                    mma_bf16(acc[mt][nt], ah[mt], Bh);
                    mma_bf16(acc[mt][nt], ah[mt], Bl);
                    mma_bf16(acc[mt][nt], al[mt], Bh);
                }
        }
        __syncthreads();   // stage t fully consumed before it is refilled at t+2
    }

    // ---- epilogue ----
    #pragma unroll
    for (int mt = 0; mt < 2; ++mt)
        #pragma unroll
        for (int nt = 0; nt < 4; ++nt)
            #pragma unroll
            for (int h = 0; h < 2; ++h) {
                const int row = row0 + wm + mt * 16 + h * 8 + (lane >> 2);
                if (row >= n_out) continue;
                const int col = wn + nt * 8 + (lane & 3) * 2;
                float v0 = acc[mt][nt][h * 2]     + __ldg(&bias[col]);
                float v1 = acc[mt][nt][h * 2 + 1] + __ldg(&bias[col + 1]);
                if (LEAKY) {
                    v0 = v0 >= 0.f ? v0 : 0.1f * v0;
                    v1 = v1 >= 0.f ? v1 : 0.1f * v1;
                }
                if (SPLIT_OUT) {
                    __nv_bfloat162 hh, ll;
                    hh.x = __float2bfloat16_rn(v0);
                    hh.y = __float2bfloat16_rn(v1);
                    ll.x = __float2bfloat16_rn(v0 - __bfloat162float(hh.x));
                    ll.y = __float2bfloat16_rn(v1 - __bfloat162float(hh.y));
                    *(uint32_t*)(o_hi + (size_t)row * 64 + col) = *(uint32_t*)&hh;
                    *(uint32_t*)(o_lo + (size_t)row * 64 + col) = *(uint32_t*)&ll;
                } else {
                    float2 v; v.x = v0; v.y = v1;
                    *(float2*)(o_f32 + (size_t)row * 64 + col) = v;
                }
            }
}

// ---------------------------------------------------------------------------
__global__ __launch_bounds__(256) void split_kernel(
    const float* __restrict__ src, __nv_bfloat16* __restrict__ hi,
    __nv_bfloat16* __restrict__ lo, int n)
{
    for (int i = blockIdx.x * 256 + threadIdx.x; i < n; i += gridDim.x * 256) {
        const float v = src[i];
        const __nv_bfloat16 h = __float2bfloat16_rn(v);
        hi[i] = h;
        lo[i] = __float2bfloat16_rn(v - __bfloat162float(h));
    }
}

__global__ __launch_bounds__(256) void bn_partial_kernel(
    const __nv_bfloat16* __restrict__ fh, const __nv_bfloat16* __restrict__ fl,
    int n2, float* __restrict__ partial)
{
    const int tid = threadIdx.x;
    const int c = tid & 63;
    const int sub = tid >> 6;
    float s = 0.f, s2 = 0.f;
    for (int r = blockIdx.x * 4 + sub; r < n2; r += gridDim.x * 4) {
        const size_t i = (size_t)r * 64 + c;
        const float v = __bfloat162float(fh[i]) + __bfloat162float(fl[i]);
        s += v; s2 += v * v;
    }
    __shared__ float sh[256], sh2[256];
    sh[tid] = s; sh2[tid] = s2;
    __syncthreads();
    if (tid < 64) {
        s  = sh[tid]  + sh[tid + 64]  + sh[tid + 128]  + sh[tid + 192];
        s2 = sh2[tid] + sh2[tid + 64] + sh2[tid + 128] + sh2[tid + 192];
        partial[blockIdx.x * 128 + tid]      = s;
        partial[blockIdx.x * 128 + 64 + tid] = s2;
    }
}

__global__ void bn_finalize_kernel(
    const float* __restrict__ partial, int G, int n2,
    const float* __restrict__ gamma, const float* __restrict__ beta,
    const float* __restrict__ scale, float* __restrict__ st)
{
    const int c = threadIdx.x;
    float s = 0.f, s2 = 0.f;
    for (int g = 0; g < G; ++g) {
        s  += partial[g * 128 + c];
        s2 += partial[g * 128 + 64 + c];
    }
    const float inv_n = 1.0f / (float)n2;
    const float mu  = s * inv_n;
    const float var = fmaxf(s2 * inv_n - mu * mu, 0.f);
    const float r   = rsqrtf(var + 1e-5f);
    const float sc  = scale[0];
    st[c]      = gamma[c] * r * sc;
    st[64 + c] = (beta[c] - mu * gamma[c] * r) * sc;
}

__global__ __launch_bounds__(256) void bn_apply_kernel(
    __nv_bfloat16* __restrict__ fh, __nv_bfloat16* __restrict__ fl,
    int n2, const float* __restrict__ st)
{
    const int i = blockIdx.x * 256 + threadIdx.x;
    if (i < n2 * 64) {
        const int c = i & 63;
        const float v = fmaf(__bfloat162float(fh[i]) + __bfloat162float(fl[i]),
                             st[c], st[64 + c]);
        const __nv_bfloat16 h = __float2bfloat16_rn(v);
        fh[i] = h;
        fl[i] = __float2bfloat16_rn(v - __bfloat162float(h));
    }
}

// ---------------------------------------------------------------------------
extern "C" void kernel_launch(void* const* d_in, const int* in_sizes, int n_in_arrs,
                              void* d_out, int out_size)
{
    const float* x     = (const float*)d_in[0];
    const float* W1    = (const float*)d_in[1];
    const float* b1    = (const float*)d_in[2];
    const float* W2    = (const float*)d_in[3];
    const float* b2    = (const float*)d_in[4];
    const float* W3    = (const float*)d_in[5];
    const float* b3    = (const float*)d_in[6];
    const float* gamma = (const float*)d_in[7];
    const float* beta  = (const float*)d_in[8];
    const float* scale = (const float*)d_in[9];
    const int* nmap1   = (const int*)d_in[10];
    const int* nmap2   = (const int*)d_in[11];
    const int* nmap3   = (const int*)d_in[12];

    const int N  = in_sizes[0] / 96;
    const int N2 = in_sizes[11] / 8;

    __nv_bfloat16 *xh, *xl, *f1h, *f1l, *f2h, *f2l, *w1h, *w1l, *w2h, *w2l, *w3h, *w3l;
    float *partial, *st;
    cudaGetSymbolAddress((void**)&xh, g_x_hi);   cudaGetSymbolAddress((void**)&xl, g_x_lo);
    cudaGetSymbolAddress((void**)&f1h, g_f1_hi); cudaGetSymbolAddress((void**)&f1l, g_f1_lo);
    cudaGetSymbolAddress((void**)&f2h, g_f2_hi); cudaGetSymbolAddress((void**)&f2l, g_f2_lo);
    cudaGetSymbolAddress((void**)&w1h, g_w1_hi); cudaGetSymbolAddress((void**)&w1l, g_w1_lo);
    cudaGetSymbolAddress((void**)&w2h, g_w2_hi); cudaGetSymbolAddress((void**)&w2l, g_w2_lo);
    cudaGetSymbolAddress((void**)&w3h, g_w3_hi); cudaGetSymbolAddress((void**)&w3l, g_w3_lo);
    cudaGetSymbolAddress((void**)&partial, g_partial);
    cudaGetSymbolAddress((void**)&st, g_st);

    split_kernel<<<512, 256>>>(x, xh, xl, N * 96);
    split_kernel<<<256, 256>>>(W1, w1h, w1l, 27 * 96 * 64);
    split_kernel<<<64,  256>>>(W2, w2h, w2l, 8 * 64 * 64);
    split_kernel<<<128, 256>>>(W3, w3h, w3l, 27 * 64 * 64);

    // conv1: 96 -> 64, 27 taps, leaky, split-out
    {
        constexpr int stage = (2 * 128 * 104 + 2 * 96 * 72) * 2;   // 80,896 B
        constexpr int smem  = 2 * stage;                           // 161,792 B
        cudaFuncSetAttribute(sconv_mma<96, 27, true, true>,
                             cudaFuncAttributeMaxDynamicSharedMemorySize, smem);
        sconv_mma<96, 27, true, true><<<(N + 127) / 128, 256, smem>>>(
            xh, xl, N, nmap1, N, w1h, w1l, b1, f1h, f1l, nullptr);
    }
    // conv2: 64 -> 64, 8 taps, leaky, split-out
    {
        constexpr int stage = (2 * 128 * 72 + 2 * 64 * 72) * 2;    // 55,296 B
        constexpr int smem  = 2 * stage;                           // 110,592 B
        cudaFuncSetAttribute(sconv_mma<64, 8, true, true>,
                             cudaFuncAttributeMaxDynamicSharedMemorySize, smem);
        sconv_mma<64, 8, true, true><<<(N2 + 127) / 128, 256, smem>>>(
            f1h, f1l, N, nmap2, N2, w2h, w2l, b2, f2h, f2l, nullptr);
    }
    // batch norm + scale, in place on f2 hi/lo
    {
        const int G = 120;
        bn_partial_kernel<<<G, 256>>>(f2h, f2l, N2, partial);
        bn_finalize_kernel<<<1, 64>>>(partial, G, N2, gamma, beta, scale, st);
        bn_apply_kernel<<<(N2 * 64 + 255) / 256, 256>>>(f2h, f2l, N2, st);
    }
    // conv3: 64 -> 64, 27 taps, fp32 out
    {
        constexpr int stage = (2 * 128 * 72 + 2 * 64 * 72) * 2;
        constexpr int smem  = 2 * stage;
        cudaFuncSetAttribute(sconv_mma<64, 27, false, false>,
                             cudaFuncAttributeMaxDynamicSharedMemorySize, smem);
        sconv_mma<64, 27, false, false><<<(N2 + 127) / 128, 256, smem>>>(
            f2h, f2l, N2, nmap3, N2, w3h, w3l, b3, nullptr, nullptr, (float*)d_out);
    }
}

// round 6
// speedup vs baseline: 2.8373x; 1.4339x over previous
#include <cuda_runtime.h>
#include <cuda_bf16.h>
#include <cstdint>

// ===========================================================================
// Sparse conv encoder, mma.sync bf16 hi/lo x3.
// conv1: per-tap COMPACTED gather-GEMM (skip invalid taps, ~5x fewer FLOPs)
// conv2/conv3: dense cp.async double-buffered tap pipeline (R5 kernel)
// ===========================================================================

#define MAXN 60032
#define NBMAX 256
#define KT1 27

__device__ __nv_bfloat16 g_x_hi[MAXN * 96];
__device__ __nv_bfloat16 g_x_lo[MAXN * 96];
__device__ __nv_bfloat16 g_f1_hi[MAXN * 64];
__device__ __nv_bfloat16 g_f1_lo[MAXN * 64];
__device__ __nv_bfloat16 g_f2_hi[MAXN * 64];
__device__ __nv_bfloat16 g_f2_lo[MAXN * 64];
__device__ __nv_bfloat16 g_w1_hi[27 * 96 * 64];
__device__ __nv_bfloat16 g_w1_lo[27 * 96 * 64];
__device__ __nv_bfloat16 g_w2_hi[8 * 64 * 64];
__device__ __nv_bfloat16 g_w2_lo[8 * 64 * 64];
__device__ __nv_bfloat16 g_w3_hi[27 * 64 * 64];
__device__ __nv_bfloat16 g_w3_lo[27 * 64 * 64];
__device__ float g_partial[128 * 128];
__device__ float g_st[128];

// conv1 compaction structures
__device__ int   g_mask[MAXN];
__device__ int   g_rowbase[MAXN];
__device__ int   g_taphist[KT1 * NBMAX];
__device__ int   g_tapblockbase[KT1 * NBMAX];
__device__ int   g_taptotal[KT1];
__device__ int   g_tapbase[KT1 + 1];
__device__ int   g_cntpart[NBMAX];
__device__ int   g_cntbase[NBMAX];
__device__ int   g_pairidx[KT1 * MAXN];
__device__ int   g_invpos[KT1 * MAXN];
__device__ float g_contrib[(size_t)KT1 * MAXN * 64];

__device__ __forceinline__ uint32_t smem_u32(const void* p) {
    uint32_t a;
    asm("{ .reg .u64 t; cvta.to.shared.u64 t, %1; cvt.u32.u64 %0, t; }"
        : "=r"(a) : "l"(p));
    return a;
}
__device__ __forceinline__ void cp16(uint32_t s, const void* g, int sz) {
    asm volatile("cp.async.cg.shared.global [%0], [%1], 16, %2;"
                 :: "r"(s), "l"(g), "r"(sz) : "memory");
}
__device__ __forceinline__ void cp_commit() {
    asm volatile("cp.async.commit_group;" ::: "memory");
}
template <int N>
__device__ __forceinline__ void cp_wait() {
    asm volatile("cp.async.wait_group %0;" :: "n"(N) : "memory");
}
__device__ __forceinline__ void ldsm_x4(uint32_t* r, uint32_t addr) {
    asm volatile("ldmatrix.sync.aligned.m8n8.x4.shared.b16 {%0,%1,%2,%3}, [%4];"
                 : "=r"(r[0]), "=r"(r[1]), "=r"(r[2]), "=r"(r[3]) : "r"(addr));
}
__device__ __forceinline__ void ldsm_x4_t(uint32_t* r, uint32_t addr) {
    asm volatile("ldmatrix.sync.aligned.m8n8.x4.trans.shared.b16 {%0,%1,%2,%3}, [%4];"
                 : "=r"(r[0]), "=r"(r[1]), "=r"(r[2]), "=r"(r[3]) : "r"(addr));
}
__device__ __forceinline__ void mma_bf16(float* d, const uint32_t* a, const uint32_t* b) {
    asm volatile(
        "mma.sync.aligned.m16n8k16.row.col.f32.bf16.bf16.f32 "
        "{%0,%1,%2,%3}, {%4,%5,%6,%7}, {%8,%9}, {%0,%1,%2,%3};"
        : "+f"(d[0]), "+f"(d[1]), "+f"(d[2]), "+f"(d[3])
        : "r"(a[0]), "r"(a[1]), "r"(a[2]), "r"(a[3]), "r"(b[0]), "r"(b[1]));
}

// ===========================================================================
// conv1 compaction prep
// ===========================================================================
__global__ __launch_bounds__(256) void mask_kernel(
    const int* __restrict__ nmap, int n, int n_in)
{
    const int b = blockIdx.x, t = threadIdx.x;
    const int lane = t & 31, w = t >> 5;
    const int row = b * 256 + t;
    unsigned m = 0;
    if (row < n) {
        #pragma unroll
        for (int k = 0; k < KT1; ++k)
            if (__ldg(&nmap[(size_t)row * KT1 + k]) < n_in) m |= 1u << k;
        g_mask[row] = (int)m;
    }
    const int cnt = __popc(m);

    __shared__ int hist[KT1];
    if (t < KT1) hist[t] = 0;
    __syncthreads();
    #pragma unroll
    for (int k = 0; k < KT1; ++k) {
        const unsigned bal = __ballot_sync(0xffffffffu, (m >> k) & 1);
        if (lane == 0 && bal) atomicAdd(&hist[k], __popc(bal));
    }
    // block sum of cnt
    int v = cnt;
    #pragma unroll
    for (int o = 16; o > 0; o >>= 1) v += __shfl_down_sync(0xffffffffu, v, o);
    __shared__ int wsum[8];
    if (lane == 0) wsum[w] = v;
    __syncthreads();
    if (t == 0) {
        int s = 0;
        #pragma unroll
        for (int i = 0; i < 8; ++i) s += wsum[i];
        g_cntpart[b] = s;
    }
    if (t < KT1) g_taphist[t * NBMAX + b] = hist[t];
}

__global__ void scan_kernel(int NB)
{
    const int t = threadIdx.x;
    if (t < KT1) {
        int s = 0;
        for (int b = 0; b < NB; ++b) {
            const int h = g_taphist[t * NBMAX + b];
            g_tapblockbase[t * NBMAX + b] = s;
            s += h;
        }
        g_taptotal[t] = s;
    }
    __syncthreads();
    if (t == 0) {
        int s = 0;
        for (int k = 0; k < KT1; ++k) { g_tapbase[k] = s; s += g_taptotal[k]; }
        g_tapbase[KT1] = s;
        int c = 0;
        for (int b = 0; b < NB; ++b) { g_cntbase[b] = c; c += g_cntpart[b]; }
    }
}

__global__ __launch_bounds__(256) void emit_kernel(
    const int* __restrict__ nmap, int n)
{
    const int b = blockIdx.x, t = threadIdx.x;
    const int lane = t & 31, w = t >> 5;
    const int row = b * 256 + t;
    const unsigned m = (row < n) ? (unsigned)g_mask[row] : 0u;
    const int cnt = __popc(m);

    // block exclusive scan of cnt -> rowbase
    int v = cnt;
    #pragma unroll
    for (int o = 1; o < 32; o <<= 1) {
        const int u = __shfl_up_sync(0xffffffffu, v, o);
        if (lane >= o) v += u;
    }
    __shared__ int ws[8];
    if (lane == 31) ws[w] = v;
    __syncthreads();
    int wbase = 0;
    for (int i = 0; i < w; ++i) wbase += ws[i];
    const int rbase = g_cntbase[b] + wbase + v - cnt;
    if (row < n) g_rowbase[row] = rbase;

    __shared__ int wt[8];
    for (int k = 0; k < KT1; ++k) {
        const int valid = (m >> k) & 1;
        const unsigned bal = __ballot_sync(0xffffffffu, valid);
        __syncthreads();
        if (lane == 0) wt[w] = __popc(bal);
        __syncthreads();
        int wb = 0;
        for (int i = 0; i < w; ++i) wb += wt[i];
        const int rank = wb + __popc(bal & ((1u << lane) - 1u));
        if (valid) {
            const int pos = g_tapbase[k] + g_tapblockbase[k * NBMAX + b] + rank;
            g_pairidx[pos] = __ldg(&nmap[(size_t)row * KT1 + k]);
            const int j = __popc(m & ((1u << k) - 1u));
            g_invpos[rbase + j] = pos;
        }
    }
}

// ===========================================================================
// conv1 compact GEMM: one tap per CTA, 128 compacted rows x 64 cols
// ===========================================================================
__global__ __launch_bounds__(256) void conv1_compact(
    const __nv_bfloat16* __restrict__ a_hi, const __nv_bfloat16* __restrict__ a_lo,
    const __nv_bfloat16* __restrict__ w_hi, const __nv_bfloat16* __restrict__ w_lo)
{
    constexpr int CIN = 96;
    constexpr int LDA = CIN + 8;
    constexpr int LDB = 72;
    constexpr int KSTEPS = CIN / 16;
    constexpr int CPR = CIN / 8;
    constexpr int A_HALVES = 128 * LDA;
    constexpr int B_HALVES = CIN * LDB;
    constexpr uint32_t OFF_ALO = (uint32_t)A_HALVES * 2;
    constexpr uint32_t OFF_BHI = (uint32_t)(2 * A_HALVES) * 2;
    constexpr uint32_t OFF_BLO = (uint32_t)(2 * A_HALVES + B_HALVES) * 2;

    const int k = blockIdx.y;
    const int tot = g_taptotal[k];
    const int tilestart = blockIdx.x * 128;
    if (tilestart >= tot) return;
    const int q0 = g_tapbase[k] + tilestart;

    extern __shared__ __align__(16) __nv_bfloat16 smem[];
    const uint32_t sb = smem_u32(smem);
    const int tid = threadIdx.x, wid = tid >> 5, lane = tid & 31;
    const int wm = (wid >> 1) * 32, wn = (wid & 1) * 32;
    const int lrow = lane & 15, lcol8 = (lane >> 4) * 8;

    // gather A (hi/lo), chunk-major coalesced; tail rows zero-filled
    #pragma unroll 2
    for (int i = tid; i < 2 * 128 * CPR; i += 256) {
        const int buf = i / (128 * CPR);
        const int j   = i % (128 * CPR);
        const int r   = j / CPR, c = j % CPR;
        const int ok  = tilestart + r < tot;
        const int idx = ok ? __ldg(&g_pairidx[q0 + r]) : 0;
        const __nv_bfloat16* src = (buf ? a_lo : a_hi) + (size_t)idx * CIN + c * 8;
        cp16(sb + (buf ? OFF_ALO : 0u) + (uint32_t)(r * LDA + c * 8) * 2,
             src, ok ? 16 : 0);
    }
    // stage B tap k (hi/lo)
    #pragma unroll 2
    for (int i = tid; i < 2 * CIN * 8; i += 256) {
        const int buf = i / (CIN * 8);
        const int j   = i % (CIN * 8);
        const int r   = j >> 3, c = j & 7;
        const __nv_bfloat16* src = (buf ? w_lo : w_hi)
            + (size_t)k * CIN * 64 + r * 64 + c * 8;
        cp16(sb + (buf ? OFF_BLO : OFF_BHI) + (uint32_t)(r * LDB + c * 8) * 2,
             src, 16);
    }
    cp_commit();
    cp_wait<0>();
    __syncthreads();

    float acc[2][4][4] = {};
    #pragma unroll
    for (int s = 0; s < KSTEPS; ++s) {
        uint32_t ah[2][4], al[2][4];
        #pragma unroll
        for (int mt = 0; mt < 2; ++mt) {
            const uint32_t off = (uint32_t)((wm + mt * 16 + lrow) * LDA
                                            + s * 16 + lcol8) * 2;
            ldsm_x4(ah[mt], sb + off);
            ldsm_x4(al[mt], sb + OFF_ALO + off);
        }
        uint32_t bh[2][4], bl[2][4];
        #pragma unroll
        for (int p = 0; p < 2; ++p) {
            const uint32_t off = (uint32_t)((s * 16 + lrow) * LDB
                                            + wn + p * 16 + lcol8) * 2;
            ldsm_x4_t(bh[p], sb + OFF_BHI + off);
            ldsm_x4_t(bl[p], sb + OFF_BLO + off);
        }
        #pragma unroll
        for (int mt = 0; mt < 2; ++mt)
            #pragma unroll
            for (int nt = 0; nt < 4; ++nt) {
                const uint32_t* Bh = &bh[nt >> 1][(nt & 1) * 2];
                const uint32_t* Bl = &bl[nt >> 1][(nt & 1) * 2];
                mma_bf16(acc[mt][nt], ah[mt], Bh);
                mma_bf16(acc[mt][nt], ah[mt], Bl);
                mma_bf16(acc[mt][nt], al[mt], Bh);
            }
    }

    // write fp32 partials to contrib (no bias/activation here)
    #pragma unroll
    for (int mt = 0; mt < 2; ++mt)
        #pragma unroll
        for (int nt = 0; nt < 4; ++nt)
            #pragma unroll
            for (int h = 0; h < 2; ++h) {
                const int rl = wm + mt * 16 + h * 8 + (lane >> 2);
                if (tilestart + rl < tot) {
                    const int col = wn + nt * 8 + (lane & 3) * 2;
                    float2 v;
                    v.x = acc[mt][nt][h * 2];
                    v.y = acc[mt][nt][h * 2 + 1];
                    *(float2*)(g_contrib + (size_t)(q0 + rl) * 64 + col) = v;
                }
            }
}

// reduce per-row contributions -> f1 (bias + leaky + bf16 hi/lo split)
__global__ __launch_bounds__(256) void reduce1_kernel(
    const float* __restrict__ bias, int n,
    __nv_bfloat16* __restrict__ o_hi, __nv_bfloat16* __restrict__ o_lo)
{
    const int row = blockIdx.x * 8 + (threadIdx.x >> 5);
    if (row >= n) return;
    const int lane = threadIdx.x & 31;
    const int cnt  = __popc((unsigned)g_mask[row]);
    const int base = g_rowbase[row];
    const int c0   = lane * 2;
    float s0 = __ldg(&bias[c0]), s1 = __ldg(&bias[c0 + 1]);
    for (int j = 0; j < cnt; ++j) {
        const int p = __ldg(&g_invpos[base + j]);
        const float2 v = *(const float2*)(g_contrib + (size_t)p * 64 + c0);
        s0 += v.x; s1 += v.y;
    }
    s0 = s0 >= 0.f ? s0 : 0.1f * s0;
    s1 = s1 >= 0.f ? s1 : 0.1f * s1;
    __nv_bfloat162 hh, ll;
    hh.x = __float2bfloat16_rn(s0);
    hh.y = __float2bfloat16_rn(s1);
    ll.x = __float2bfloat16_rn(s0 - __bfloat162float(hh.x));
    ll.y = __float2bfloat16_rn(s1 - __bfloat162float(hh.y));
    *(uint32_t*)(o_hi + (size_t)row * 64 + c0) = *(uint32_t*)&hh;
    *(uint32_t*)(o_lo + (size_t)row * 64 + c0) = *(uint32_t*)&ll;
}

// ===========================================================================
// Dense gather-GEMM (conv2/conv3): R5 kernel, 2-stage cp.async tap pipeline
// ===========================================================================
template <int CIN, int KT, bool LEAKY, bool SPLIT_OUT>
__global__ __launch_bounds__(256) void sconv_mma(
    const __nv_bfloat16* __restrict__ a_hi, const __nv_bfloat16* __restrict__ a_lo,
    int n_in, const int* __restrict__ nmap, int n_out,
    const __nv_bfloat16* __restrict__ w_hi, const __nv_bfloat16* __restrict__ w_lo,
    const float* __restrict__ bias,
    __nv_bfloat16* __restrict__ o_hi, __nv_bfloat16* __restrict__ o_lo,
    float* __restrict__ o_f32)
{
    constexpr int LDA = CIN + 8;
    constexpr int LDB = 72;
    constexpr int KSTEPS = CIN / 16;
    constexpr int CPR = CIN / 8;
    constexpr int A_HALVES = 128 * LDA;
    constexpr int B_HALVES = CIN * LDB;
    constexpr uint32_t OFF_ALO = (uint32_t)A_HALVES * 2;
    constexpr uint32_t OFF_BHI = (uint32_t)(2 * A_HALVES) * 2;
    constexpr uint32_t OFF_BLO = (uint32_t)(2 * A_HALVES + B_HALVES) * 2;
    constexpr uint32_t STAGE   = (uint32_t)(2 * A_HALVES + 2 * B_HALVES) * 2;

    extern __shared__ __align__(16) __nv_bfloat16 smem[];
    const uint32_t sb = smem_u32(smem);

    const int tid  = threadIdx.x;
    const int wid  = tid >> 5;
    const int lane = tid & 31;
    const int row0 = blockIdx.x * 128;
    const int wm   = (wid >> 1) * 32;
    const int wn   = (wid & 1) * 32;
    const int lrow = lane & 15, lcol8 = (lane >> 4) * 8;

    float acc[2][4][4] = {};

    auto prefetch = [&](int t, uint32_t stoff) {
        #pragma unroll 2
        for (int i = tid; i < 2 * 128 * CPR; i += 256) {
            const int buf = i / (128 * CPR);
            const int j   = i % (128 * CPR);
            const int r   = j / CPR, c = j % CPR;
            const int rr  = row0 + r;
            int idx = n_in;
            if (rr < n_out) idx = __ldg(&nmap[(size_t)rr * KT + t]);
            const int ok = idx < n_in;
            const __nv_bfloat16* src = (buf ? a_lo : a_hi)
                + (size_t)(ok ? idx : 0) * CIN + c * 8;
            cp16(sb + stoff + (buf ? OFF_ALO : 0u)
                 + (uint32_t)(r * LDA + c * 8) * 2, src, ok ? 16 : 0);
        }
        #pragma unroll 2
        for (int i = tid; i < 2 * CIN * 8; i += 256) {
            const int buf = i / (CIN * 8);
            const int j   = i % (CIN * 8);
            const int r   = j >> 3, c = j & 7;
            const __nv_bfloat16* src = (buf ? w_lo : w_hi)
                + (size_t)t * CIN * 64 + r * 64 + c * 8;
            cp16(sb + stoff + (buf ? OFF_BLO : OFF_BHI)
                 + (uint32_t)(r * LDB + c * 8) * 2, src, 16);
        }
    };

    prefetch(0, 0);
    cp_commit();

    for (int t = 0; t < KT; ++t) {
        const uint32_t stoff = (t & 1) ? STAGE : 0u;
        if (t + 1 < KT) {
            prefetch(t + 1, (t & 1) ? 0u : STAGE);
            cp_commit();
            cp_wait<1>();
        } else {
            cp_wait<0>();
        }
        __syncthreads();

        #pragma unroll
        for (int s = 0; s < KSTEPS; ++s) {
            uint32_t ah[2][4], al[2][4];
            #pragma unroll
            for (int mt = 0; mt < 2; ++mt) {
                const uint32_t off = (uint32_t)((wm + mt * 16 + lrow) * LDA
                                                + s * 16 + lcol8) * 2;
                ldsm_x4(ah[mt], sb + stoff + off);
                ldsm_x4(al[mt], sb + stoff + OFF_ALO + off);
            }
            uint32_t bh[2][4], bl[2][4];
            #pragma unroll
            for (int p = 0; p < 2; ++p) {
                const uint32_t off = (uint32_t)((s * 16 + lrow) * LDB
                                                + wn + p * 16 + lcol8) * 2;
                ldsm_x4_t(bh[p], sb + stoff + OFF_BHI + off);
                ldsm_x4_t(bl[p], sb + stoff + OFF_BLO + off);
            }
            #pragma unroll
            for (int mt = 0; mt < 2; ++mt)
                #pragma unroll
                for (int nt = 0; nt < 4; ++nt) {
                    const uint32_t* Bh = &bh[nt >> 1][(nt & 1) * 2];
                    const uint32_t* Bl = &bl[nt >> 1][(nt & 1) * 2];
                    mma_bf16(acc[mt][nt], ah[mt], Bh);
                    mma_bf16(acc[mt][nt], ah[mt], Bl);
                    mma_bf16(acc[mt][nt], al[mt], Bh);
                }
        }
        __syncthreads();
    }

    #pragma unroll
    for (int mt = 0; mt < 2; ++mt)
        #pragma unroll
        for (int nt = 0; nt < 4; ++nt)
            #pragma unroll
            for (int h = 0; h < 2; ++h) {
                const int row = row0 + wm + mt * 16 + h * 8 + (lane >> 2);
                if (row >= n_out) continue;
                const int col = wn + nt * 8 + (lane & 3) * 2;
                float v0 = acc[mt][nt][h * 2]     + __ldg(&bias[col]);
                float v1 = acc[mt][nt][h * 2 + 1] + __ldg(&bias[col + 1]);
                if (LEAKY) {
                    v0 = v0 >= 0.f ? v0 : 0.1f * v0;
                    v1 = v1 >= 0.f ? v1 : 0.1f * v1;
                }
                if (SPLIT_OUT) {
                    __nv_bfloat162 hh, ll;
                    hh.x = __float2bfloat16_rn(v0);
                    hh.y = __float2bfloat16_rn(v1);
                    ll.x = __float2bfloat16_rn(v0 - __bfloat162float(hh.x));
                    ll.y = __float2bfloat16_rn(v1 - __bfloat162float(hh.y));
                    *(uint32_t*)(o_hi + (size_t)row * 64 + col) = *(uint32_t*)&hh;
                    *(uint32_t*)(o_lo + (size_t)row * 64 + col) = *(uint32_t*)&ll;
                } else {
                    float2 v; v.x = v0; v.y = v1;
                    *(float2*)(o_f32 + (size_t)row * 64 + col) = v;
                }
            }
}

// ---------------------------------------------------------------------------
__global__ __launch_bounds__(256) void split_kernel(
    const float* __restrict__ src, __nv_bfloat16* __restrict__ hi,
    __nv_bfloat16* __restrict__ lo, int n)
{
    for (int i = blockIdx.x * 256 + threadIdx.x; i < n; i += gridDim.x * 256) {
        const float v = src[i];
        const __nv_bfloat16 h = __float2bfloat16_rn(v);
        hi[i] = h;
        lo[i] = __float2bfloat16_rn(v - __bfloat162float(h));
    }
}

__global__ __launch_bounds__(256) void bn_partial_kernel(
    const __nv_bfloat16* __restrict__ fh, const __nv_bfloat16* __restrict__ fl,
    int n2, float* __restrict__ partial)
{
    const int tid = threadIdx.x;
    const int c = tid & 63;
    const int sub = tid >> 6;
    float s = 0.f, s2 = 0.f;
    for (int r = blockIdx.x * 4 + sub; r < n2; r += gridDim.x * 4) {
        const size_t i = (size_t)r * 64 + c;
        const float v = __bfloat162float(fh[i]) + __bfloat162float(fl[i]);
        s += v; s2 += v * v;
    }
    __shared__ float sh[256], sh2[256];
    sh[tid] = s; sh2[tid] = s2;
    __syncthreads();
    if (tid < 64) {
        s  = sh[tid]  + sh[tid + 64]  + sh[tid + 128]  + sh[tid + 192];
        s2 = sh2[tid] + sh2[tid + 64] + sh2[tid + 128] + sh2[tid + 192];
        partial[blockIdx.x * 128 + tid]      = s;
        partial[blockIdx.x * 128 + 64 + tid] = s2;
    }
}

__global__ void bn_finalize_kernel(
    const float* __restrict__ partial, int G, int n2,
    const float* __restrict__ gamma, const float* __restrict__ beta,
    const float* __restrict__ scale, float* __restrict__ st)
{
    const int c = threadIdx.x;
    float s = 0.f, s2 = 0.f;
    for (int g = 0; g < G; ++g) {
        s  += partial[g * 128 + c];
        s2 += partial[g * 128 + 64 + c];
    }
    const float inv_n = 1.0f / (float)n2;
    const float mu  = s * inv_n;
    const float var = fmaxf(s2 * inv_n - mu * mu, 0.f);
    const float r   = rsqrtf(var + 1e-5f);
    const float sc  = scale[0];
    st[c]      = gamma[c] * r * sc;
    st[64 + c] = (beta[c] - mu * gamma[c] * r) * sc;
}

__global__ __launch_bounds__(256) void bn_apply_kernel(
    __nv_bfloat16* __restrict__ fh, __nv_bfloat16* __restrict__ fl,
    int n2, const float* __restrict__ st)
{
    const int i = blockIdx.x * 256 + threadIdx.x;
    if (i < n2 * 64) {
        const int c = i & 63;
        const float v = fmaf(__bfloat162float(fh[i]) + __bfloat162float(fl[i]),
                             st[c], st[64 + c]);
        const __nv_bfloat16 h = __float2bfloat16_rn(v);
        fh[i] = h;
        fl[i] = __float2bfloat16_rn(v - __bfloat162float(h));
    }
}

// ---------------------------------------------------------------------------
extern "C" void kernel_launch(void* const* d_in, const int* in_sizes, int n_in_arrs,
                              void* d_out, int out_size)
{
    const float* x     = (const float*)d_in[0];
    const float* W1    = (const float*)d_in[1];
    const float* b1    = (const float*)d_in[2];
    const float* W2    = (const float*)d_in[3];
    const float* b2    = (const float*)d_in[4];
    const float* W3    = (const float*)d_in[5];
    const float* b3    = (const float*)d_in[6];
    const float* gamma = (const float*)d_in[7];
    const float* beta  = (const float*)d_in[8];
    const float* scale = (const float*)d_in[9];
    const int* nmap1   = (const int*)d_in[10];
    const int* nmap2   = (const int*)d_in[11];
    const int* nmap3   = (const int*)d_in[12];

    const int N  = in_sizes[0] / 96;
    const int N2 = in_sizes[11] / 8;
    const int NB = (N + 255) / 256;

    __nv_bfloat16 *xh, *xl, *f1h, *f1l, *f2h, *f2l, *w1h, *w1l, *w2h, *w2l, *w3h, *w3l;
    float *partial, *st;
    cudaGetSymbolAddress((void**)&xh, g_x_hi);   cudaGetSymbolAddress((void**)&xl, g_x_lo);
    cudaGetSymbolAddress((void**)&f1h, g_f1_hi); cudaGetSymbolAddress((void**)&f1l, g_f1_lo);
    cudaGetSymbolAddress((void**)&f2h, g_f2_hi); cudaGetSymbolAddress((void**)&f2l, g_f2_lo);
    cudaGetSymbolAddress((void**)&w1h, g_w1_hi); cudaGetSymbolAddress((void**)&w1l, g_w1_lo);
    cudaGetSymbolAddress((void**)&w2h, g_w2_hi); cudaGetSymbolAddress((void**)&w2l, g_w2_lo);
    cudaGetSymbolAddress((void**)&w3h, g_w3_hi); cudaGetSymbolAddress((void**)&w3l, g_w3_lo);
    cudaGetSymbolAddress((void**)&partial, g_partial);
    cudaGetSymbolAddress((void**)&st, g_st);

    split_kernel<<<512, 256>>>(x, xh, xl, N * 96);
    split_kernel<<<256, 256>>>(W1, w1h, w1l, 27 * 96 * 64);
    split_kernel<<<64,  256>>>(W2, w2h, w2l, 8 * 64 * 64);
    split_kernel<<<128, 256>>>(W3, w3h, w3l, 27 * 64 * 64);

    // ---- conv1: compacted path ----
    mask_kernel<<<NB, 256>>>(nmap1, N, N);
    scan_kernel<<<1, 256>>>(NB);
    emit_kernel<<<NB, 256>>>(nmap1, N);
    {
        constexpr int smem = (2 * 128 * 104 + 2 * 96 * 72) * 2;   // 80,896 B
        cudaFuncSetAttribute(conv1_compact,
                             cudaFuncAttributeMaxDynamicSharedMemorySize, smem);
        dim3 grid((N + 127) / 128, KT1);
        conv1_compact<<<grid, 256, smem>>>(xh, xl, w1h, w1l);
    }
    reduce1_kernel<<<(N + 7) / 8, 256>>>(b1, N, f1h, f1l);

    // ---- conv2: dense, 8 taps ----
    {
        constexpr int stage = (2 * 128 * 72 + 2 * 64 * 72) * 2;
        constexpr int smem  = 2 * stage;
        cudaFuncSetAttribute(sconv_mma<64, 8, true, true>,
                             cudaFuncAttributeMaxDynamicSharedMemorySize, smem);
        sconv_mma<64, 8, true, true><<<(N2 + 127) / 128, 256, smem>>>(
            f1h, f1l, N, nmap2, N2, w2h, w2l, b2, f2h, f2l, nullptr);
    }
    // ---- batch norm + scale ----
    {
        const int G = 120;
        bn_partial_kernel<<<G, 256>>>(f2h, f2l, N2, partial);
        bn_finalize_kernel<<<1, 64>>>(partial, G, N2, gamma, beta, scale, st);
        bn_apply_kernel<<<(N2 * 64 + 255) / 256, 256>>>(f2h, f2l, N2, st);
    }
    // ---- conv3: dense, 27 taps, fp32 out ----
    {
        constexpr int stage = (2 * 128 * 72 + 2 * 64 * 72) * 2;
        constexpr int smem  = 2 * stage;
        cudaFuncSetAttribute(sconv_mma<64, 27, false, false>,
                             cudaFuncAttributeMaxDynamicSharedMemorySize, smem);
        sconv_mma<64, 27, false, false><<<(N2 + 127) / 128, 256, smem>>>(
            f2h, f2l, N2, nmap3, N2, w3h, w3l, b3, nullptr, nullptr, (float*)d_out);
    }
}

// round 7
// speedup vs baseline: 3.1041x; 1.0940x over previous
#include <cuda_runtime.h>
#include <cuda_bf16.h>
#include <cstdint>

// ===========================================================================
// Sparse conv encoder, mma.sync bf16 hi/lo x3.
// conv1: per-tap COMPACTED gather-GEMM; conv2/conv3 dense pipelined.
// R7: parallel warp-scan replaces the serial single-block scan.
// ===========================================================================

#define MAXN 60032
#define NBMAX 256
#define KT1 27

__device__ __nv_bfloat16 g_x_hi[MAXN * 96];
__device__ __nv_bfloat16 g_x_lo[MAXN * 96];
__device__ __nv_bfloat16 g_f1_hi[MAXN * 64];
__device__ __nv_bfloat16 g_f1_lo[MAXN * 64];
__device__ __nv_bfloat16 g_f2_hi[MAXN * 64];
__device__ __nv_bfloat16 g_f2_lo[MAXN * 64];
__device__ __nv_bfloat16 g_w1_hi[27 * 96 * 64];
__device__ __nv_bfloat16 g_w1_lo[27 * 96 * 64];
__device__ __nv_bfloat16 g_w2_hi[8 * 64 * 64];
__device__ __nv_bfloat16 g_w2_lo[8 * 64 * 64];
__device__ __nv_bfloat16 g_w3_hi[27 * 64 * 64];
__device__ __nv_bfloat16 g_w3_lo[27 * 64 * 64];
__device__ float g_partial[128 * 128];
__device__ float g_st[128];

// conv1 compaction structures
__device__ int   g_mask[MAXN];
__device__ int   g_rowbase[MAXN];
__device__ int   g_taphist[KT1 * NBMAX];
__device__ int   g_tapblockbase[KT1 * NBMAX];
__device__ int   g_taptotal[KT1];
__device__ int   g_tapbase[KT1 + 1];
__device__ int   g_cntpart[NBMAX];
__device__ int   g_cntbase[NBMAX];
__device__ int   g_pairidx[KT1 * MAXN];
__device__ int   g_invpos[KT1 * MAXN];
__device__ float g_contrib[(size_t)KT1 * MAXN * 64];

__device__ __forceinline__ uint32_t smem_u32(const void* p) {
    uint32_t a;
    asm("{ .reg .u64 t; cvta.to.shared.u64 t, %1; cvt.u32.u64 %0, t; }"
        : "=r"(a) : "l"(p));
    return a;
}
__device__ __forceinline__ void cp16(uint32_t s, const void* g, int sz) {
    asm volatile("cp.async.cg.shared.global [%0], [%1], 16, %2;"
                 :: "r"(s), "l"(g), "r"(sz) : "memory");
}
__device__ __forceinline__ void cp_commit() {
    asm volatile("cp.async.commit_group;" ::: "memory");
}
template <int N>
__device__ __forceinline__ void cp_wait() {
    asm volatile("cp.async.wait_group %0;" :: "n"(N) : "memory");
}
__device__ __forceinline__ void ldsm_x4(uint32_t* r, uint32_t addr) {
    asm volatile("ldmatrix.sync.aligned.m8n8.x4.shared.b16 {%0,%1,%2,%3}, [%4];"
                 : "=r"(r[0]), "=r"(r[1]), "=r"(r[2]), "=r"(r[3]) : "r"(addr));
}
__device__ __forceinline__ void ldsm_x4_t(uint32_t* r, uint32_t addr) {
    asm volatile("ldmatrix.sync.aligned.m8n8.x4.trans.shared.b16 {%0,%1,%2,%3}, [%4];"
                 : "=r"(r[0]), "=r"(r[1]), "=r"(r[2]), "=r"(r[3]) : "r"(addr));
}
__device__ __forceinline__ void mma_bf16(float* d, const uint32_t* a, const uint32_t* b) {
    asm volatile(
        "mma.sync.aligned.m16n8k16.row.col.f32.bf16.bf16.f32 "
        "{%0,%1,%2,%3}, {%4,%5,%6,%7}, {%8,%9}, {%0,%1,%2,%3};"
        : "+f"(d[0]), "+f"(d[1]), "+f"(d[2]), "+f"(d[3])
        : "r"(a[0]), "r"(a[1]), "r"(a[2]), "r"(a[3]), "r"(b[0]), "r"(b[1]));
}
__device__ __forceinline__ int wscan_incl(int v, int lane) {
    #pragma unroll
    for (int o = 1; o < 32; o <<= 1) {
        const int u = __shfl_up_sync(0xffffffffu, v, o);
        if (lane >= o) v += u;
    }
    return v;
}

// ===========================================================================
// conv1 compaction prep
// ===========================================================================
__global__ __launch_bounds__(256) void mask_kernel(
    const int* __restrict__ nmap, int n, int n_in)
{
    const int b = blockIdx.x, t = threadIdx.x;
    const int lane = t & 31, w = t >> 5;
    const int row = b * 256 + t;
    unsigned m = 0;
    if (row < n) {
        #pragma unroll
        for (int k = 0; k < KT1; ++k)
            if (__ldg(&nmap[(size_t)row * KT1 + k]) < n_in) m |= 1u << k;
        g_mask[row] = (int)m;
    }
    const int cnt = __popc(m);

    __shared__ int hist[KT1];
    if (t < KT1) hist[t] = 0;
    __syncthreads();
    #pragma unroll
    for (int k = 0; k < KT1; ++k) {
        const unsigned bal = __ballot_sync(0xffffffffu, (m >> k) & 1);
        if (lane == 0 && bal) atomicAdd(&hist[k], __popc(bal));
    }
    int v = cnt;
    #pragma unroll
    for (int o = 16; o > 0; o >>= 1) v += __shfl_down_sync(0xffffffffu, v, o);
    __shared__ int wsum[8];
    if (lane == 0) wsum[w] = v;
    __syncthreads();
    if (t == 0) {
        int s = 0;
        #pragma unroll
        for (int i = 0; i < 8; ++i) s += wsum[i];
        g_cntpart[b] = s;
    }
    if (t < KT1) g_taphist[t * NBMAX + b] = hist[t];
}

// Parallel scan: warps 0..KT1-1 scan per-tap block histograms; warp KT1 scans
// cntpart; warp 0 then scans the 27 tap totals. One block, 896 threads.
__global__ __launch_bounds__(896) void scan_kernel(int NB)
{
    const int tid = threadIdx.x, w = tid >> 5, lane = tid & 31;
    if (w < KT1) {
        int s = 0;
        for (int b0 = 0; b0 < NB; b0 += 32) {
            const int b = b0 + lane;
            const int h = (b < NB) ? g_taphist[w * NBMAX + b] : 0;
            const int inc = wscan_incl(h, lane);
            if (b < NB) g_tapblockbase[w * NBMAX + b] = s + inc - h;
            s += __shfl_sync(0xffffffffu, inc, 31);
        }
        if (lane == 0) g_taptotal[w] = s;
    } else if (w == KT1) {
        int s = 0;
        for (int b0 = 0; b0 < NB; b0 += 32) {
            const int b = b0 + lane;
            const int h = (b < NB) ? g_cntpart[b] : 0;
            const int inc = wscan_incl(h, lane);
            if (b < NB) g_cntbase[b] = s + inc - h;
            s += __shfl_sync(0xffffffffu, inc, 31);
        }
    }
    __syncthreads();
    if (w == 0) {
        const int v = (lane < KT1) ? g_taptotal[lane] : 0;
        const int inc = wscan_incl(v, lane);
        if (lane <= KT1) g_tapbase[lane] = inc - v;
    }
}

__global__ __launch_bounds__(256) void emit_kernel(
    const int* __restrict__ nmap, int n)
{
    const int b = blockIdx.x, t = threadIdx.x;
    const int lane = t & 31, w = t >> 5;
    const int row = b * 256 + t;
    const unsigned m = (row < n) ? (unsigned)g_mask[row] : 0u;
    const int cnt = __popc(m);

    int v = cnt;
    #pragma unroll
    for (int o = 1; o < 32; o <<= 1) {
        const int u = __shfl_up_sync(0xffffffffu, v, o);
        if (lane >= o) v += u;
    }
    __shared__ int ws[8];
    if (lane == 31) ws[w] = v;
    __syncthreads();
    int wbase = 0;
    for (int i = 0; i < w; ++i) wbase += ws[i];
    const int rbase = g_cntbase[b] + wbase + v - cnt;
    if (row < n) g_rowbase[row] = rbase;

    __shared__ int wt[8];
    for (int k = 0; k < KT1; ++k) {
        const int valid = (m >> k) & 1;
        const unsigned bal = __ballot_sync(0xffffffffu, valid);
        __syncthreads();
        if (lane == 0) wt[w] = __popc(bal);
        __syncthreads();
        int wb = 0;
        for (int i = 0; i < w; ++i) wb += wt[i];
        const int rank = wb + __popc(bal & ((1u << lane) - 1u));
        if (valid) {
            const int pos = g_tapbase[k] + g_tapblockbase[k * NBMAX + b] + rank;
            g_pairidx[pos] = __ldg(&nmap[(size_t)row * KT1 + k]);
            const int j = __popc(m & ((1u << k) - 1u));
            g_invpos[rbase + j] = pos;
        }
    }
}

// ===========================================================================
// conv1 compact GEMM: one tap per CTA, 128 compacted rows x 64 cols
// ===========================================================================
__global__ __launch_bounds__(256) void conv1_compact(
    const __nv_bfloat16* __restrict__ a_hi, const __nv_bfloat16* __restrict__ a_lo,
    const __nv_bfloat16* __restrict__ w_hi, const __nv_bfloat16* __restrict__ w_lo)
{
    constexpr int CIN = 96;
    constexpr int LDA = CIN + 8;
    constexpr int LDB = 72;
    constexpr int KSTEPS = CIN / 16;
    constexpr int CPR = CIN / 8;
    constexpr int A_HALVES = 128 * LDA;
    constexpr int B_HALVES = CIN * LDB;
    constexpr uint32_t OFF_ALO = (uint32_t)A_HALVES * 2;
    constexpr uint32_t OFF_BHI = (uint32_t)(2 * A_HALVES) * 2;
    constexpr uint32_t OFF_BLO = (uint32_t)(2 * A_HALVES + B_HALVES) * 2;

    const int k = blockIdx.y;
    const int tot = g_taptotal[k];
    const int tilestart = blockIdx.x * 128;
    if (tilestart >= tot) return;
    const int q0 = g_tapbase[k] + tilestart;

    extern __shared__ __align__(16) __nv_bfloat16 smem[];
    const uint32_t sb = smem_u32(smem);
    const int tid = threadIdx.x, wid = tid >> 5, lane = tid & 31;
    const int wm = (wid >> 1) * 32, wn = (wid & 1) * 32;
    const int lrow = lane & 15, lcol8 = (lane >> 4) * 8;

    #pragma unroll 2
    for (int i = tid; i < 2 * 128 * CPR; i += 256) {
        const int buf = i / (128 * CPR);
        const int j   = i % (128 * CPR);
        const int r   = j / CPR, c = j % CPR;
        const int ok  = tilestart + r < tot;
        const int idx = ok ? __ldg(&g_pairidx[q0 + r]) : 0;
        const __nv_bfloat16* src = (buf ? a_lo : a_hi) + (size_t)idx * CIN + c * 8;
        cp16(sb + (buf ? OFF_ALO : 0u) + (uint32_t)(r * LDA + c * 8) * 2,
             src, ok ? 16 : 0);
    }
    #pragma unroll 2
    for (int i = tid; i < 2 * CIN * 8; i += 256) {
        const int buf = i / (CIN * 8);
        const int j   = i % (CIN * 8);
        const int r   = j >> 3, c = j & 7;
        const __nv_bfloat16* src = (buf ? w_lo : w_hi)
            + (size_t)k * CIN * 64 + r * 64 + c * 8;
        cp16(sb + (buf ? OFF_BLO : OFF_BHI) + (uint32_t)(r * LDB + c * 8) * 2,
             src, 16);
    }
    cp_commit();
    cp_wait<0>();
    __syncthreads();

    float acc[2][4][4] = {};
    #pragma unroll
    for (int s = 0; s < KSTEPS; ++s) {
        uint32_t ah[2][4], al[2][4];
        #pragma unroll
        for (int mt = 0; mt < 2; ++mt) {
            const uint32_t off = (uint32_t)((wm + mt * 16 + lrow) * LDA
                                            + s * 16 + lcol8) * 2;
            ldsm_x4(ah[mt], sb + off);
            ldsm_x4(al[mt], sb + OFF_ALO + off);
        }
        uint32_t bh[2][4], bl[2][4];
        #pragma unroll
        for (int p = 0; p < 2; ++p) {
            const uint32_t off = (uint32_t)((s * 16 + lrow) * LDB
                                            + wn + p * 16 + lcol8) * 2;
            ldsm_x4_t(bh[p], sb + OFF_BHI + off);
            ldsm_x4_t(bl[p], sb + OFF_BLO + off);
        }
        #pragma unroll
        for (int mt = 0; mt < 2; ++mt)
            #pragma unroll
            for (int nt = 0; nt < 4; ++nt) {
                const uint32_t* Bh = &bh[nt >> 1][(nt & 1) * 2];
                const uint32_t* Bl = &bl[nt >> 1][(nt & 1) * 2];
                mma_bf16(acc[mt][nt], ah[mt], Bh);
                mma_bf16(acc[mt][nt], ah[mt], Bl);
                mma_bf16(acc[mt][nt], al[mt], Bh);
            }
    }

    #pragma unroll
    for (int mt = 0; mt < 2; ++mt)
        #pragma unroll
        for (int nt = 0; nt < 4; ++nt)
            #pragma unroll
            for (int h = 0; h < 2; ++h) {
                const int rl = wm + mt * 16 + h * 8 + (lane >> 2);
                if (tilestart + rl < tot) {
                    const int col = wn + nt * 8 + (lane & 3) * 2;
                    float2 v;
                    v.x = acc[mt][nt][h * 2];
                    v.y = acc[mt][nt][h * 2 + 1];
                    *(float2*)(g_contrib + (size_t)(q0 + rl) * 64 + col) = v;
                }
            }
}

__global__ __launch_bounds__(256) void reduce1_kernel(
    const float* __restrict__ bias, int n,
    __nv_bfloat16* __restrict__ o_hi, __nv_bfloat16* __restrict__ o_lo)
{
    const int row = blockIdx.x * 8 + (threadIdx.x >> 5);
    if (row >= n) return;
    const int lane = threadIdx.x & 31;
    const int cnt  = __popc((unsigned)g_mask[row]);
    const int base = g_rowbase[row];
    const int c0   = lane * 2;
    float s0 = __ldg(&bias[c0]), s1 = __ldg(&bias[c0 + 1]);
    for (int j = 0; j < cnt; ++j) {
        const int p = __ldg(&g_invpos[base + j]);
        const float2 v = *(const float2*)(g_contrib + (size_t)p * 64 + c0);
        s0 += v.x; s1 += v.y;
    }
    s0 = s0 >= 0.f ? s0 : 0.1f * s0;
    s1 = s1 >= 0.f ? s1 : 0.1f * s1;
    __nv_bfloat162 hh, ll;
    hh.x = __float2bfloat16_rn(s0);
    hh.y = __float2bfloat16_rn(s1);
    ll.x = __float2bfloat16_rn(s0 - __bfloat162float(hh.x));
    ll.y = __float2bfloat16_rn(s1 - __bfloat162float(hh.y));
    *(uint32_t*)(o_hi + (size_t)row * 64 + c0) = *(uint32_t*)&hh;
    *(uint32_t*)(o_lo + (size_t)row * 64 + c0) = *(uint32_t*)&ll;
}

// ===========================================================================
// Dense gather-GEMM (conv2/conv3): 2-stage cp.async tap pipeline
// ===========================================================================
template <int CIN, int KT, bool LEAKY, bool SPLIT_OUT>
__global__ __launch_bounds__(256) void sconv_mma(
    const __nv_bfloat16* __restrict__ a_hi, const __nv_bfloat16* __restrict__ a_lo,
    int n_in, const int* __restrict__ nmap, int n_out,
    const __nv_bfloat16* __restrict__ w_hi, const __nv_bfloat16* __restrict__ w_lo,
    const float* __restrict__ bias,
    __nv_bfloat16* __restrict__ o_hi, __nv_bfloat16* __restrict__ o_lo,
    float* __restrict__ o_f32)
{
    constexpr int LDA = CIN + 8;
    constexpr int LDB = 72;
    constexpr int KSTEPS = CIN / 16;
    constexpr int CPR = CIN / 8;
    constexpr int A_HALVES = 128 * LDA;
    constexpr int B_HALVES = CIN * LDB;
    constexpr uint32_t OFF_ALO = (uint32_t)A_HALVES * 2;
    constexpr uint32_t OFF_BHI = (uint32_t)(2 * A_HALVES) * 2;
    constexpr uint32_t OFF_BLO = (uint32_t)(2 * A_HALVES + B_HALVES) * 2;
    constexpr uint32_t STAGE   = (uint32_t)(2 * A_HALVES + 2 * B_HALVES) * 2;

    extern __shared__ __align__(16) __nv_bfloat16 smem[];
    const uint32_t sb = smem_u32(smem);

    const int tid  = threadIdx.x;
    const int wid  = tid >> 5;
    const int lane = tid & 31;
    const int row0 = blockIdx.x * 128;
    const int wm   = (wid >> 1) * 32;
    const int wn   = (wid & 1) * 32;
    const int lrow = lane & 15, lcol8 = (lane >> 4) * 8;

    float acc[2][4][4] = {};

    auto prefetch = [&](int t, uint32_t stoff) {
        #pragma unroll 2
        for (int i = tid; i < 2 * 128 * CPR; i += 256) {
            const int buf = i / (128 * CPR);
            const int j   = i % (128 * CPR);
            const int r   = j / CPR, c = j % CPR;
            const int rr  = row0 + r;
            int idx = n_in;
            if (rr < n_out) idx = __ldg(&nmap[(size_t)rr * KT + t]);
            const int ok = idx < n_in;
            const __nv_bfloat16* src = (buf ? a_lo : a_hi)
                + (size_t)(ok ? idx : 0) * CIN + c * 8;
            cp16(sb + stoff + (buf ? OFF_ALO : 0u)
                 + (uint32_t)(r * LDA + c * 8) * 2, src, ok ? 16 : 0);
        }
        #pragma unroll 2
        for (int i = tid; i < 2 * CIN * 8; i += 256) {
            const int buf = i / (CIN * 8);
            const int j   = i % (CIN * 8);
            const int r   = j >> 3, c = j & 7;
            const __nv_bfloat16* src = (buf ? w_lo : w_hi)
                + (size_t)t * CIN * 64 + r * 64 + c * 8;
            cp16(sb + stoff + (buf ? OFF_BLO : OFF_BHI)
                 + (uint32_t)(r * LDB + c * 8) * 2, src, 16);
        }
    };

    prefetch(0, 0);
    cp_commit();

    for (int t = 0; t < KT; ++t) {
        const uint32_t stoff = (t & 1) ? STAGE : 0u;
        if (t + 1 < KT) {
            prefetch(t + 1, (t & 1) ? 0u : STAGE);
            cp_commit();
            cp_wait<1>();
        } else {
            cp_wait<0>();
        }
        __syncthreads();

        #pragma unroll
        for (int s = 0; s < KSTEPS; ++s) {
            uint32_t ah[2][4], al[2][4];
            #pragma unroll
            for (int mt = 0; mt < 2; ++mt) {
                const uint32_t off = (uint32_t)((wm + mt * 16 + lrow) * LDA
                                                + s * 16 + lcol8) * 2;
                ldsm_x4(ah[mt], sb + stoff + off);
                ldsm_x4(al[mt], sb + stoff + OFF_ALO + off);
            }
            uint32_t bh[2][4], bl[2][4];
            #pragma unroll
            for (int p = 0; p < 2; ++p) {
                const uint32_t off = (uint32_t)((s * 16 + lrow) * LDB
                                                + wn + p * 16 + lcol8) * 2;
                ldsm_x4_t(bh[p], sb + stoff + OFF_BHI + off);
                ldsm_x4_t(bl[p], sb + stoff + OFF_BLO + off);
            }
            #pragma unroll
            for (int mt = 0; mt < 2; ++mt)
                #pragma unroll
                for (int nt = 0; nt < 4; ++nt) {
                    const uint32_t* Bh = &bh[nt >> 1][(nt & 1) * 2];
                    const uint32_t* Bl = &bl[nt >> 1][(nt & 1) * 2];
                    mma_bf16(acc[mt][nt], ah[mt], Bh);
                    mma_bf16(acc[mt][nt], ah[mt], Bl);
                    mma_bf16(acc[mt][nt], al[mt], Bh);
                }
        }
        __syncthreads();
    }

    #pragma unroll
    for (int mt = 0; mt < 2; ++mt)
        #pragma unroll
        for (int nt = 0; nt < 4; ++nt)
            #pragma unroll
            for (int h = 0; h < 2; ++h) {
                const int row = row0 + wm + mt * 16 + h * 8 + (lane >> 2);
                if (row >= n_out) continue;
                const int col = wn + nt * 8 + (lane & 3) * 2;
                float v0 = acc[mt][nt][h * 2]     + __ldg(&bias[col]);
                float v1 = acc[mt][nt][h * 2 + 1] + __ldg(&bias[col + 1]);
                if (LEAKY) {
                    v0 = v0 >= 0.f ? v0 : 0.1f * v0;
                    v1 = v1 >= 0.f ? v1 : 0.1f * v1;
                }
                if (SPLIT_OUT) {
                    __nv_bfloat162 hh, ll;
                    hh.x = __float2bfloat16_rn(v0);
                    hh.y = __float2bfloat16_rn(v1);
                    ll.x = __float2bfloat16_rn(v0 - __bfloat162float(hh.x));
                    ll.y = __float2bfloat16_rn(v1 - __bfloat162float(hh.y));
                    *(uint32_t*)(o_hi + (size_t)row * 64 + col) = *(uint32_t*)&hh;
                    *(uint32_t*)(o_lo + (size_t)row * 64 + col) = *(uint32_t*)&ll;
                } else {
                    float2 v; v.x = v0; v.y = v1;
                    *(float2*)(o_f32 + (size_t)row * 64 + col) = v;
                }
            }
}

// ---------------------------------------------------------------------------
__global__ __launch_bounds__(256) void split_kernel(
    const float* __restrict__ src, __nv_bfloat16* __restrict__ hi,
    __nv_bfloat16* __restrict__ lo, int n)
{
    for (int i = blockIdx.x * 256 + threadIdx.x; i < n; i += gridDim.x * 256) {
        const float v = src[i];
        const __nv_bfloat16 h = __float2bfloat16_rn(v);
        hi[i] = h;
        lo[i] = __float2bfloat16_rn(v - __bfloat162float(h));
    }
}

__global__ __launch_bounds__(256) void bn_partial_kernel(
    const __nv_bfloat16* __restrict__ fh, const __nv_bfloat16* __restrict__ fl,
    int n2, float* __restrict__ partial)
{
    const int tid = threadIdx.x;
    const int c = tid & 63;
    const int sub = tid >> 6;
    float s = 0.f, s2 = 0.f;
    for (int r = blockIdx.x * 4 + sub; r < n2; r += gridDim.x * 4) {
        const size_t i = (size_t)r * 64 + c;
        const float v = __bfloat162float(fh[i]) + __bfloat162float(fl[i]);
        s += v; s2 += v * v;
    }
    __shared__ float sh[256], sh2[256];
    sh[tid] = s; sh2[tid] = s2;
    __syncthreads();
    if (tid < 64) {
        s  = sh[tid]  + sh[tid + 64]  + sh[tid + 128]  + sh[tid + 192];
        s2 = sh2[tid] + sh2[tid + 64] + sh2[tid + 128] + sh2[tid + 192];
        partial[blockIdx.x * 128 + tid]      = s;
        partial[blockIdx.x * 128 + 64 + tid] = s2;
    }
}

__global__ void bn_finalize_kernel(
    const float* __restrict__ partial, int G, int n2,
    const float* __restrict__ gamma, const float* __restrict__ beta,
    const float* __restrict__ scale, float* __restrict__ st)
{
    const int c = threadIdx.x;
    float s = 0.f, s2 = 0.f;
    for (int g = 0; g < G; ++g) {
        s  += partial[g * 128 + c];
        s2 += partial[g * 128 + 64 + c];
    }
    const float inv_n = 1.0f / (float)n2;
    const float mu  = s * inv_n;
    const float var = fmaxf(s2 * inv_n - mu * mu, 0.f);
    const float r   = rsqrtf(var + 1e-5f);
    const float sc  = scale[0];
    st[c]      = gamma[c] * r * sc;
    st[64 + c] = (beta[c] - mu * gamma[c] * r) * sc;
}

__global__ __launch_bounds__(256) void bn_apply_kernel(
    __nv_bfloat16* __restrict__ fh, __nv_bfloat16* __restrict__ fl,
    int n2, const float* __restrict__ st)
{
    const int i = blockIdx.x * 256 + threadIdx.x;
    if (i < n2 * 64) {
        const int c = i & 63;
        const float v = fmaf(__bfloat162float(fh[i]) + __bfloat162float(fl[i]),
                             st[c], st[64 + c]);
        const __nv_bfloat16 h = __float2bfloat16_rn(v);
        fh[i] = h;
        fl[i] = __float2bfloat16_rn(v - __bfloat162float(h));
    }
}

// ---------------------------------------------------------------------------
extern "C" void kernel_launch(void* const* d_in, const int* in_sizes, int n_in_arrs,
                              void* d_out, int out_size)
{
    const float* x     = (const float*)d_in[0];
    const float* W1    = (const float*)d_in[1];
    const float* b1    = (const float*)d_in[2];
    const float* W2    = (const float*)d_in[3];
    const float* b2    = (const float*)d_in[4];
    const float* W3    = (const float*)d_in[5];
    const float* b3    = (const float*)d_in[6];
    const float* gamma = (const float*)d_in[7];
    const float* beta  = (const float*)d_in[8];
    const float* scale = (const float*)d_in[9];
    const int* nmap1   = (const int*)d_in[10];
    const int* nmap2   = (const int*)d_in[11];
    const int* nmap3   = (const int*)d_in[12];

    const int N  = in_sizes[0] / 96;
    const int N2 = in_sizes[11] / 8;
    const int NB = (N + 255) / 256;

    __nv_bfloat16 *xh, *xl, *f1h, *f1l, *f2h, *f2l, *w1h, *w1l, *w2h, *w2l, *w3h, *w3l;
    float *partial, *st;
    cudaGetSymbolAddress((void**)&xh, g_x_hi);   cudaGetSymbolAddress((void**)&xl, g_x_lo);
    cudaGetSymbolAddress((void**)&f1h, g_f1_hi); cudaGetSymbolAddress((void**)&f1l, g_f1_lo);
    cudaGetSymbolAddress((void**)&f2h, g_f2_hi); cudaGetSymbolAddress((void**)&f2l, g_f2_lo);
    cudaGetSymbolAddress((void**)&w1h, g_w1_hi); cudaGetSymbolAddress((void**)&w1l, g_w1_lo);
    cudaGetSymbolAddress((void**)&w2h, g_w2_hi); cudaGetSymbolAddress((void**)&w2l, g_w2_lo);
    cudaGetSymbolAddress((void**)&w3h, g_w3_hi); cudaGetSymbolAddress((void**)&w3l, g_w3_lo);
    cudaGetSymbolAddress((void**)&partial, g_partial);
    cudaGetSymbolAddress((void**)&st, g_st);

    split_kernel<<<512, 256>>>(x, xh, xl, N * 96);
    split_kernel<<<256, 256>>>(W1, w1h, w1l, 27 * 96 * 64);
    split_kernel<<<64,  256>>>(W2, w2h, w2l, 8 * 64 * 64);
    split_kernel<<<128, 256>>>(W3, w3h, w3l, 27 * 64 * 64);

    // ---- conv1: compacted path ----
    mask_kernel<<<NB, 256>>>(nmap1, N, N);
    scan_kernel<<<1, 896>>>(NB);
    emit_kernel<<<NB, 256>>>(nmap1, N);
    {
        constexpr int smem = (2 * 128 * 104 + 2 * 96 * 72) * 2;   // 80,896 B
        cudaFuncSetAttribute(conv1_compact,
                             cudaFuncAttributeMaxDynamicSharedMemorySize, smem);
        dim3 grid((N + 127) / 128, KT1);
        conv1_compact<<<grid, 256, smem>>>(xh, xl, w1h, w1l);
    }
    reduce1_kernel<<<(N + 7) / 8, 256>>>(b1, N, f1h, f1l);

    // ---- conv2: dense, 8 taps ----
    {
        constexpr int stage = (2 * 128 * 72 + 2 * 64 * 72) * 2;
        constexpr int smem  = 2 * stage;
        cudaFuncSetAttribute(sconv_mma<64, 8, true, true>,
                             cudaFuncAttributeMaxDynamicSharedMemorySize, smem);
        sconv_mma<64, 8, true, true><<<(N2 + 127) / 128, 256, smem>>>(
            f1h, f1l, N, nmap2, N2, w2h, w2l, b2, f2h, f2l, nullptr);
    }
    // ---- batch norm + scale ----
    {
        const int G = 120;
        bn_partial_kernel<<<G, 256>>>(f2h, f2l, N2, partial);
        bn_finalize_kernel<<<1, 64>>>(partial, G, N2, gamma, beta, scale, st);
        bn_apply_kernel<<<(N2 * 64 + 255) / 256, 256>>>(f2h, f2l, N2, st);
    }
    // ---- conv3: dense, 27 taps, fp32 out ----
    {
        constexpr int stage = (2 * 128 * 72 + 2 * 64 * 72) * 2;
        constexpr int smem  = 2 * stage;
        cudaFuncSetAttribute(sconv_mma<64, 27, false, false>,
                             cudaFuncAttributeMaxDynamicSharedMemorySize, smem);
        sconv_mma<64, 27, false, false><<<(N2 + 127) / 128, 256, smem>>>(
            f2h, f2l, N2, nmap3, N2, w3h, w3l, b3, nullptr, nullptr, (float*)d_out);
    }
}